// round 10
// baseline (speedup 1.0000x reference)
#include <cuda_runtime.h>
#include <cuda_bf16.h>
#include <cstdint>
#include <math.h>

#define SEQ   2048
#define BATCH 2
#define HID   1024
#define NHEAD 8
#define HDIM  128
#define ROWS  (BATCH*SEQ)   /* 4096 */
#define N6    (6*HID)       /* 6144 */
#define N3    (3*HID)       /* 3072 */

/* ---------------- scratch (device globals; no allocation allowed) ------- */
__device__ float g_fused[(size_t)ROWS*N6];   /* gate section fp32 (cols<3072) */
__device__ float g_y[(size_t)ROWS*HID];
__device__ int   g_mask_int;

/* bf16x2-split operands for mma.sync GEMMs */
__device__ __nv_bfloat16 g_ah[(size_t)ROWS*HID];
__device__ __nv_bfloat16 g_al[(size_t)ROWS*HID];
__device__ __nv_bfloat16 g_wqh[(size_t)N6*HID];
__device__ __nv_bfloat16 g_wql[(size_t)N6*HID];
__device__ __nv_bfloat16 g_woh[(size_t)HID*N3];
__device__ __nv_bfloat16 g_wol[(size_t)HID*N3];
__device__ __nv_bfloat16 g_ch[(size_t)ROWS*N3];     /* gated attn out hi */
__device__ __nv_bfloat16 g_cl[(size_t)ROWS*N3];     /* gated attn out lo */

/* attention operands: q/qr/k/kr/v bf16 hi/lo, layout [row][h*128+d] */
__device__ __nv_bfloat16 g_qh[(size_t)ROWS*HID],  g_ql[(size_t)ROWS*HID];
__device__ __nv_bfloat16 g_qrh[(size_t)ROWS*HID], g_qrl[(size_t)ROWS*HID];
__device__ __nv_bfloat16 g_kh[(size_t)ROWS*HID],  g_kl[(size_t)ROWS*HID];
__device__ __nv_bfloat16 g_krh[(size_t)ROWS*HID], g_krl[(size_t)ROWS*HID];
__device__ __nv_bfloat16 g_vh[(size_t)ROWS*HID],  g_vl[(size_t)ROWS*HID];

/* ================= helpers ============================================= */
__device__ __forceinline__ uint32_t smem_u32(const void* p) {
    uint32_t a;
    asm("{ .reg .u64 t; cvta.to.shared.u64 t, %1; cvt.u32.u64 %0, t; }"
        : "=r"(a) : "l"(p));
    return a;
}
__device__ __forceinline__ void cp16(uint32_t saddr, const void* g) {
    asm volatile("cp.async.cg.shared.global [%0], [%1], 16;"
                 :: "r"(saddr), "l"(g));
}
#define CP_COMMIT() asm volatile("cp.async.commit_group;" ::: "memory")
#define CP_WAIT0()  asm volatile("cp.async.wait_group 0;" ::: "memory")
#define CP_WAIT1()  asm volatile("cp.async.wait_group 1;" ::: "memory")

__device__ __forceinline__ void ldm_x4(uint32_t* r, uint32_t addr) {
    asm volatile("ldmatrix.sync.aligned.m8n8.x4.shared.b16 {%0,%1,%2,%3}, [%4];"
                 : "=r"(r[0]), "=r"(r[1]), "=r"(r[2]), "=r"(r[3]) : "r"(addr));
}
__device__ __forceinline__ void ldm_x2(uint32_t* r, uint32_t addr) {
    asm volatile("ldmatrix.sync.aligned.m8n8.x2.shared.b16 {%0,%1}, [%2];"
                 : "=r"(r[0]), "=r"(r[1]) : "r"(addr));
}
__device__ __forceinline__ void ldm_x4_t(uint32_t* r, uint32_t addr) {
    asm volatile("ldmatrix.sync.aligned.m8n8.x4.trans.shared.b16 {%0,%1,%2,%3}, [%4];"
                 : "=r"(r[0]), "=r"(r[1]), "=r"(r[2]), "=r"(r[3]) : "r"(addr));
}
__device__ __forceinline__ void mma_bf16(float* d,
                                         const uint32_t* a,
                                         uint32_t b0, uint32_t b1) {
    asm volatile("mma.sync.aligned.m16n8k16.row.col.f32.bf16.bf16.f32 "
                 "{%0,%1,%2,%3},{%4,%5,%6,%7},{%8,%9},{%0,%1,%2,%3};"
                 : "+f"(d[0]), "+f"(d[1]), "+f"(d[2]), "+f"(d[3])
                 : "r"(a[0]), "r"(a[1]), "r"(a[2]), "r"(a[3]), "r"(b0), "r"(b1));
}
__device__ __forceinline__ void split_pair(float x0, float x1,
                                           __nv_bfloat16* ph, __nv_bfloat16* pl) {
    __nv_bfloat16 h0 = __float2bfloat16(x0), h1 = __float2bfloat16(x1);
    *(__nv_bfloat162*)ph = __nv_bfloat162(h0, h1);
    *(__nv_bfloat162*)pl = __nv_bfloat162(__float2bfloat16(x0 - __bfloat162float(h0)),
                                          __float2bfloat16(x1 - __bfloat162float(h1)));
}

/* ========== cp.async double-buffered mma.sync GEMM: C = A @ B^T ======== */
/* Block 128x128, BK=32, 8 warps (2m x 4n).                                */
/* EPI 0: QKVU — silu, then per-section: gate->fp32 C; v->split; q/k->RoPE */
/*        + split (fused rope).  EPI 1: + bias + resid -> fp32 C.          */
#define TSTR   40
#define GTILE  10240                    /* 128*TSTR*2 bytes */
#define GSTAGE (4*GTILE)
#define GSMEM  (2*GSTAGE)               /* 81920 */

template<int KDIM, int NDIM, int EPI>
__global__ __launch_bounds__(256)
void mma_gemm(const __nv_bfloat16* __restrict__ Ah, const __nv_bfloat16* __restrict__ Al,
              const __nv_bfloat16* __restrict__ Bh, const __nv_bfloat16* __restrict__ Bl,
              float* __restrict__ C,
              const float* __restrict__ bias, const float* __restrict__ resid)
{
    extern __shared__ char dsm[];
    const uint32_t sb = smem_u32(dsm);

    const int tid  = threadIdx.x;
    const int lane = tid & 31, wid = tid >> 5;
    const int wm = wid >> 2, wn = wid & 3;
    const int m0 = blockIdx.y * 128, n0 = blockIdx.x * 128;

    const int a_r = lane & 15;
    const int a_c = (lane >> 4) * 8;
    const int b_r = (lane & 7) + ((lane >> 4) & 1) * 8;
    const int b_c = ((lane >> 3) & 1) * 8;

    float acc[4][4][4];
#pragma unroll
    for (int i = 0; i < 4; i++)
#pragma unroll
        for (int j = 0; j < 4; j++)
#pragma unroll
            for (int r = 0; r < 4; r++) acc[i][j][r] = 0.f;

    const int NC = KDIM / 32;

    /* prefetch chunk 0 */
    {
        uint32_t bs = sb;
#pragma unroll
        for (int i = 0; i < 2; i++) {
            int idx = tid + 256 * i;
            int row = idx >> 2, seg = (idx & 3) << 3;
            size_t ga = (size_t)(m0 + row) * KDIM + seg;
            size_t gb = (size_t)(n0 + row) * KDIM + seg;
            uint32_t so = (uint32_t)(row * TSTR + seg) * 2;
            cp16(bs + 0*GTILE + so, Ah + ga);
            cp16(bs + 1*GTILE + so, Al + ga);
            cp16(bs + 2*GTILE + so, Bh + gb);
            cp16(bs + 3*GTILE + so, Bl + gb);
        }
        CP_COMMIT();
    }

    for (int ic = 0; ic < NC; ic++) {
        if (ic + 1 < NC) {
            int kc = (ic + 1) * 32;
            uint32_t bs = sb + ((ic + 1) & 1) * GSTAGE;
#pragma unroll
            for (int i = 0; i < 2; i++) {
                int idx = tid + 256 * i;
                int row = idx >> 2, seg = (idx & 3) << 3;
                size_t ga = (size_t)(m0 + row) * KDIM + kc + seg;
                size_t gb = (size_t)(n0 + row) * KDIM + kc + seg;
                uint32_t so = (uint32_t)(row * TSTR + seg) * 2;
                cp16(bs + 0*GTILE + so, Ah + ga);
                cp16(bs + 1*GTILE + so, Al + ga);
                cp16(bs + 2*GTILE + so, Bh + gb);
                cp16(bs + 3*GTILE + so, Bl + gb);
            }
            CP_COMMIT();
            CP_WAIT1();
        } else {
            CP_WAIT0();
        }
        __syncthreads();

        const uint32_t bs = sb + (ic & 1) * GSTAGE;
        const uint32_t uAh = bs, uAl = bs + GTILE;
        const uint32_t uBh = bs + 2*GTILE, uBl = bs + 3*GTILE;

#pragma unroll
        for (int k0 = 0; k0 < 32; k0 += 16) {
            uint32_t fAh[4][4], fAl[4][4], fB[2][4];
#pragma unroll
            for (int mt = 0; mt < 4; mt++)
                ldm_x4(fAh[mt], uAh + (uint32_t)((wm*64 + mt*16 + a_r) * TSTR + k0 + a_c) * 2);
#pragma unroll
            for (int bp = 0; bp < 2; bp++)
                ldm_x4(fB[bp], uBh + (uint32_t)((wn*32 + bp*16 + b_r) * TSTR + k0 + b_c) * 2);
#pragma unroll
            for (int mt = 0; mt < 4; mt++)
#pragma unroll
                for (int nt = 0; nt < 4; nt++)
                    mma_bf16(acc[mt][nt], fAh[mt],
                             fB[nt>>1][(nt&1)*2], fB[nt>>1][(nt&1)*2+1]);
#pragma unroll
            for (int mt = 0; mt < 4; mt++)
                ldm_x4(fAl[mt], uAl + (uint32_t)((wm*64 + mt*16 + a_r) * TSTR + k0 + a_c) * 2);
#pragma unroll
            for (int mt = 0; mt < 4; mt++)
#pragma unroll
                for (int nt = 0; nt < 4; nt++)
                    mma_bf16(acc[mt][nt], fAl[mt],
                             fB[nt>>1][(nt&1)*2], fB[nt>>1][(nt&1)*2+1]);
#pragma unroll
            for (int bp = 0; bp < 2; bp++)
                ldm_x4(fB[bp], uBl + (uint32_t)((wn*32 + bp*16 + b_r) * TSTR + k0 + b_c) * 2);
#pragma unroll
            for (int mt = 0; mt < 4; mt++)
#pragma unroll
                for (int nt = 0; nt < 4; nt++)
                    mma_bf16(acc[mt][nt], fAh[mt],
                             fB[nt>>1][(nt&1)*2], fB[nt>>1][(nt&1)*2+1]);
        }
        __syncthreads();
    }

    const int er = lane >> 2, ec = (lane & 3) * 2;
#pragma unroll
    for (int mt = 0; mt < 4; mt++) {
#pragma unroll
        for (int nt = 0; nt < 4; nt++) {
            int col = n0 + wn*32 + nt*8 + ec;
#pragma unroll
            for (int half = 0; half < 2; half++) {
                size_t row = (size_t)(m0 + wm*64 + mt*16 + er + half*8);
                float v0 = acc[mt][nt][half*2 + 0];
                float v1 = acc[mt][nt][half*2 + 1];
                if (EPI == 0) {
                    float s0 = v0 / (1.f + expf(-v0));
                    float s1 = v1 / (1.f + expf(-v1));
                    if (col < 3*HID) {
                        /* gate section: fp32 for attn epilogue */
                        float2 o; o.x = s0; o.y = s1;
                        *(float2*)&C[row * NDIM + col] = o;
                    } else if (col < 4*HID) {
                        int d = col - 3*HID;
                        split_pair(s0, s1, g_vh + row*HID + d, g_vl + row*HID + d);
                    } else {
                        /* q or k section: fused RoPE (cols are a (2i,2i+1) pair) */
                        int d = col & (HID - 1);
                        int i = (d & 127) >> 1;
                        float ang = (float)(row & (SEQ - 1))
                                  / powf(10000.f, (float)i / 64.f);
                        float sn, cs;
                        sincosf(ang, &sn, &cs);
                        float r0 = s0 * cs - s1 * sn;
                        float r1 = s1 * cs + s0 * sn;
                        size_t o = row * HID + d;
                        if (col < 5*HID) {
                            split_pair(s0, s1, g_qh  + o, g_ql  + o);
                            split_pair(r0, r1, g_qrh + o, g_qrl + o);
                        } else {
                            split_pair(s0, s1, g_kh  + o, g_kl  + o);
                            split_pair(r0, r1, g_krh + o, g_krl + o);
                        }
                    }
                } else {
                    size_t rb = row * NDIM + col;
                    float2 o;
                    o.x = v0 + bias[col+0] + resid[rb+0];
                    o.y = v1 + bias[col+1] + resid[rb+1];
                    *(float2*)&C[row * NDIM + col] = o;
                }
            }
        }
    }
}

/* ============ fp32 -> bf16 hi/lo conversions =========================== */
__global__ __launch_bounds__(256)
void conv_split(const float* __restrict__ A, __nv_bfloat16* __restrict__ H,
                __nv_bfloat16* __restrict__ L, int n4)
{
    int i = blockIdx.x * 256 + threadIdx.x;
    if (i >= n4) return;
    float4 v = *(const float4*)(A + (size_t)i * 4);
    split_pair(v.x, v.y, H + (size_t)i*4,     L + (size_t)i*4);
    split_pair(v.z, v.w, H + (size_t)i*4 + 2, L + (size_t)i*4 + 2);
}

__global__ __launch_bounds__(256)
void conv_split_T(const float* __restrict__ W, __nv_bfloat16* __restrict__ Th,
                  __nv_bfloat16* __restrict__ Tl, int K, int N)
{
    __shared__ float t[32][33];
    int kb = blockIdx.y * 32, nb = blockIdx.x * 32;
    int tx = threadIdx.x & 31, ty = threadIdx.x >> 5;
#pragma unroll
    for (int i = 0; i < 4; i++) {
        int k = ty + 8 * i;
        t[k][tx] = W[(size_t)(kb + k) * N + nb + tx];
    }
    __syncthreads();
#pragma unroll
    for (int i = 0; i < 4; i++) {
        int n = ty + 8 * i;
        float v = t[tx][n];
        __nv_bfloat16 h = __float2bfloat16(v);
        size_t o = (size_t)(nb + n) * K + kb + tx;
        Th[o] = h;
        Tl[o] = __float2bfloat16(v - __bfloat162float(h));
    }
}

/* ---------------- mask dtype detector ---------------------------------- */
__global__ void mask_detect_kernel(const unsigned char* __restrict__ mask)
{
    __shared__ int cnt;
    if (threadIdx.x == 0) cnt = 0;
    __syncthreads();
    int c = 0;
    for (int i = threadIdx.x; i < 16384; i += 256) c += (mask[i] != 0);
    atomicAdd(&cnt, c);
    __syncthreads();
    if (threadIdx.x == 0) g_mask_int = (cnt < 4096) ? 1 : 0;
}

/* ---------------- tensor-core 3-way attention (512 thr, pipelined) ----- */
#define KSTR 136   /* K/V/Q smem row stride (bf16): 128 + 8 */
#define SSTR 40    /* S smem row stride: 32 + 8 */
#define KTILE 8704 /* 32*KSTR*2 */

/* smem byte offsets */
#define O_QH   0
#define O_QL   17408
#define O_QRH  34816
#define O_QRL  52224
#define O_KV   69632
#define KV_STAGE (6*KTILE)      /* 52224 */
#define O_SRH  174080
#define O_SRL  179200
#define O_STH  184320
#define O_STL  189440
#define O_SPH  194560
#define O_SPL  199680
#define O_MK   204800
#define ASMEM  206848

__global__ __launch_bounds__(512)
void attn_mma(const unsigned char* __restrict__ mask,
              const float* __restrict__ bias,
              __nv_bfloat16* __restrict__ ch, __nv_bfloat16* __restrict__ cl)
{
    extern __shared__ char sm[];
    const uint32_t sb = smem_u32(sm);
    unsigned char* MKb = (unsigned char*)(sm + O_MK);

    const int b = blockIdx.z, h = blockIdx.y, q0 = blockIdx.x * 64;
    const int tid = threadIdx.x, lane = tid & 31, wid = tid >> 5;
    const int wq = wid >> 2, wx = wid & 3;     /* 16 warps: 4 q-sub x 4 x */
    const int mint = g_mask_int;
    const float inv_s = 1.0f / (float)SEQ;

    const int a_r = lane & 15, a_c = (lane >> 4) * 8;
    const int b_r = lane & 7,  b_c = ((lane >> 3) & 1) * 8;
    const int er  = lane >> 2, ec  = (lane & 3) * 2;

    /* persistent Q tiles: 64 rows x 128 cols, 1024 chunks per tile */
#pragma unroll
    for (int i = 0; i < 2; i++) {
        int c = tid + 512 * i;
        int row = c >> 4, seg = (c & 15) * 8;
        size_t g = (size_t)(b * SEQ + q0 + row) * HID + h * 128 + seg;
        int so = (row * KSTR + seg) * 2;
        *(uint4*)(sm + O_QH  + so) = *(const uint4*)&g_qh[g];
        *(uint4*)(sm + O_QL  + so) = *(const uint4*)&g_ql[g];
        *(uint4*)(sm + O_QRH + so) = *(const uint4*)&g_qrh[g];
        *(uint4*)(sm + O_QRL + so) = *(const uint4*)&g_qrl[g];
    }

    /* accB[sec][j][4]: rows wq*16, cols wx*32 + j*8 */
    float accB[3][4][4];
#pragma unroll
    for (int s = 0; s < 3; s++)
#pragma unroll
        for (int j = 0; j < 4; j++)
#pragma unroll
            for (int r = 0; r < 4; r++) accB[s][j][r] = 0.f;

    const int NIT = SEQ / 32;

    /* prefetch KV tiles for m-iter 0 (512 chunks, one per thread) */
    {
        uint32_t bs = sb + O_KV;
        int row = tid >> 4, seg = (tid & 15) * 8;
        size_t g = (size_t)(b * SEQ + row) * HID + h * 128 + seg;
        uint32_t so = (uint32_t)(row * KSTR + seg) * 2;
        cp16(bs + 0*KTILE + so, g_kh  + g);
        cp16(bs + 1*KTILE + so, g_kl  + g);
        cp16(bs + 2*KTILE + so, g_krh + g);
        cp16(bs + 3*KTILE + so, g_krl + g);
        cp16(bs + 4*KTILE + so, g_vh  + g);
        cp16(bs + 5*KTILE + so, g_vl  + g);
        CP_COMMIT();
    }
    __syncthreads();   /* Q tiles visible */

    for (int it = 0; it < NIT; it++) {
        const int m0 = it * 32;

        /* prefetch next m-tile */
        if (it + 1 < NIT) {
            uint32_t bs = sb + O_KV + ((it + 1) & 1) * KV_STAGE;
            int mn = (it + 1) * 32;
            int row = tid >> 4, seg = (tid & 15) * 8;
            size_t g = (size_t)(b * SEQ + mn + row) * HID + h * 128 + seg;
            uint32_t so = (uint32_t)(row * KSTR + seg) * 2;
            cp16(bs + 0*KTILE + so, g_kh  + g);
            cp16(bs + 1*KTILE + so, g_kl  + g);
            cp16(bs + 2*KTILE + so, g_krh + g);
            cp16(bs + 3*KTILE + so, g_krl + g);
            cp16(bs + 4*KTILE + so, g_vh  + g);
            cp16(bs + 5*KTILE + so, g_vl  + g);
            CP_COMMIT();
        }

        /* mask tile + ts scores: 64x32 entries, 4 per thread */
        {
            int n = tid >> 3, seg = (tid & 7) * 4;
            size_t gi = ((size_t)b * SEQ + q0 + n) * SEQ + m0 + seg;
            float4 bv = *(const float4*)&bias[gi];
            float mf[4];
            if (mint) {
                int4 mi = *(const int4*)&((const int*)mask)[gi];
                mf[0]=mi.x?1.f:0.f; mf[1]=mi.y?1.f:0.f;
                mf[2]=mi.z?1.f:0.f; mf[3]=mi.w?1.f:0.f;
            } else {
                uchar4 mu = *(const uchar4*)&mask[gi];
                mf[0]=mu.x?1.f:0.f; mf[1]=mu.y?1.f:0.f;
                mf[2]=mu.z?1.f:0.f; mf[3]=mu.w?1.f:0.f;
            }
#pragma unroll
            for (int j = 0; j < 4; j++) MKb[n * 32 + seg + j] = (unsigned char)mf[j];
            __nv_bfloat16* TH = (__nv_bfloat16*)(sm + O_STH);
            __nv_bfloat16* TL = (__nv_bfloat16*)(sm + O_STL);
            split_pair(mf[0] * bv.x, mf[1] * bv.y,
                       TH + n * SSTR + seg,     TL + n * SSTR + seg);
            split_pair(mf[2] * bv.z, mf[3] * bv.w,
                       TH + n * SSTR + seg + 2, TL + n * SSTR + seg + 2);
        }

        if (it + 1 < NIT) { CP_WAIT1(); } else { CP_WAIT0(); }
        __syncthreads();   /* KV(it) + MK/ST visible */

        const uint32_t kb = sb + O_KV + (it & 1) * KV_STAGE;

        /* phase A: each warp one 16x8 tile; plain (v=0), rope (v=1) */
#pragma unroll
        for (int v = 0; v < 2; v++) {
            const uint32_t uQh = sb + (v ? O_QRH : O_QH);
            const uint32_t uQl = sb + (v ? O_QRL : O_QL);
            const uint32_t uKh = kb + (v ? 2*KTILE : 0);
            const uint32_t uKl = kb + (v ? 3*KTILE : 1*KTILE);
            float acc[4];
#pragma unroll
            for (int r = 0; r < 4; r++) acc[r] = 0.f;

#pragma unroll
            for (int k16 = 0; k16 < 8; k16++) {
                int k0 = k16 * 16;
                uint32_t fAh[4], fAl[4], fBh[2], fBl[2];
                ldm_x4(fAh, uQh + (uint32_t)((wq*16 + a_r) * KSTR + k0 + a_c) * 2);
                ldm_x4(fAl, uQl + (uint32_t)((wq*16 + a_r) * KSTR + k0 + a_c) * 2);
                ldm_x2(fBh, uKh + (uint32_t)((wx*8 + b_r) * KSTR + k0 + b_c) * 2);
                ldm_x2(fBl, uKl + (uint32_t)((wx*8 + b_r) * KSTR + k0 + b_c) * 2);
                mma_bf16(acc, fAh, fBh[0], fBh[1]);
                mma_bf16(acc, fAl, fBh[0], fBh[1]);
                mma_bf16(acc, fAh, fBl[0], fBl[1]);
            }
            __nv_bfloat16* SH = (__nv_bfloat16*)(sm + (v ? O_SRH : O_SPH));
            __nv_bfloat16* SL = (__nv_bfloat16*)(sm + (v ? O_SRL : O_SPL));
#pragma unroll
            for (int half = 0; half < 2; half++) {
                int r = wq*16 + er + half*8;
                int c = wx*8 + ec;
                float f0 = (float)MKb[r*32 + c];
                float f1 = (float)MKb[r*32 + c + 1];
                float s0 = f0 * fmaxf(acc[half*2 + 0], 0.f) * inv_s;
                float s1 = f1 * fmaxf(acc[half*2 + 1], 0.f) * inv_s;
                split_pair(s0, s1, SH + r*SSTR + c, SL + r*SSTR + c);
            }
        }
        __syncthreads();

        /* phase B: warp (wq, wx): rows wq*16, cols wx*32, all 3 secs */
        const uint32_t uSH[3] = {sb + O_SRH, sb + O_STH, sb + O_SPH};
        const uint32_t uSL[3] = {sb + O_SRL, sb + O_STL, sb + O_SPL};
        const uint32_t uVh = kb + 4*KTILE, uVl = kb + 5*KTILE;
#pragma unroll
        for (int k16 = 0; k16 < 2; k16++) {
            int k0 = k16 * 16;
            uint32_t fVh[2][4], fVl[2][4];
#pragma unroll
            for (int dh = 0; dh < 2; dh++) {
                ldm_x4_t(fVh[dh], uVh + (uint32_t)((k0 + a_r) * KSTR + wx*32 + dh*16 + a_c) * 2);
                ldm_x4_t(fVl[dh], uVl + (uint32_t)((k0 + a_r) * KSTR + wx*32 + dh*16 + a_c) * 2);
            }
#pragma unroll
            for (int sec = 0; sec < 3; sec++) {
                uint32_t fSh[4], fSl[4];
                ldm_x4(fSh, uSH[sec] + (uint32_t)((wq*16 + a_r) * SSTR + k0 + a_c) * 2);
                ldm_x4(fSl, uSL[sec] + (uint32_t)((wq*16 + a_r) * SSTR + k0 + a_c) * 2);
#pragma unroll
                for (int j = 0; j < 4; j++) {
                    uint32_t bh0 = fVh[j>>1][(j&1)*2], bh1 = fVh[j>>1][(j&1)*2+1];
                    uint32_t bl0 = fVl[j>>1][(j&1)*2], bl1 = fVl[j>>1][(j&1)*2+1];
                    mma_bf16(accB[sec][j], fSh, bh0, bh1);
                    mma_bf16(accB[sec][j], fSl, bh0, bh1);
                    mma_bf16(accB[sec][j], fSh, bl0, bl1);
                }
            }
        }
        __syncthreads();   /* all tiles consumed before next prefetch */
    }

    /* final epilogue: * gate, bf16-split into ch/cl                       */
#pragma unroll
    for (int sec = 0; sec < 3; sec++) {
#pragma unroll
        for (int j = 0; j < 4; j++) {
#pragma unroll
            for (int half = 0; half < 2; half++) {
                int rl = wq*16 + er + half*8;
                size_t grow = (size_t)(b * SEQ + q0 + rl);
                int d = wx*32 + j*8 + ec;
                int cx = h*384 + sec*128 + d;
                float2 g = *(const float2*)&g_fused[grow * N6 + cx];
                float o0 = accB[sec][j][half*2 + 0] * g.x;
                float o1 = accB[sec][j][half*2 + 1] * g.y;
                split_pair(o0, o1, ch + grow * N3 + cx, cl + grow * N3 + cx);
            }
        }
    }
}

/* ---------------- RMSNorm --------------------------------------------- */
__global__ __launch_bounds__(256)
void rms_kernel(const float* __restrict__ y, const float* __restrict__ w,
                float* __restrict__ out)
{
    __shared__ float sh[8];
    __shared__ float tot;
    int row = blockIdx.x;
    const float* yr = y + (size_t)row * HID;
    float ss = 0.f;
    for (int i = threadIdx.x; i < HID; i += 256) {
        float v = yr[i];
        ss = fmaf(v, v, ss);
    }
#pragma unroll
    for (int o = 16; o > 0; o >>= 1) ss += __shfl_down_sync(0xffffffffu, ss, o);
    if ((threadIdx.x & 31) == 0) sh[threadIdx.x >> 5] = ss;
    __syncthreads();
    if (threadIdx.x == 0) {
        float t = 0.f;
#pragma unroll
        for (int i = 0; i < 8; i++) t += sh[i];
        tot = rsqrtf(t / (float)HID + 1e-6f);
    }
    __syncthreads();
    float r = tot;
    for (int i = threadIdx.x; i < HID; i += 256)
        out[(size_t)row * HID + i] = yr[i] * r * w[i];
}

/* ---------------- launch ----------------------------------------------- */
extern "C" void kernel_launch(void* const* d_in, const int* in_sizes, int n_in,
                              void* d_out, int out_size)
{
    const float*         hidden = (const float*)d_in[0];
    const unsigned char* mask   = (const unsigned char*)d_in[1];
    const float*         bias   = (const float*)d_in[2];
    const float*         Wqkvu  = (const float*)d_in[3];
    const float*         Wout   = (const float*)d_in[4];
    const float*         bout   = (const float*)d_in[5];
    const float*         rmsw   = (const float*)d_in[6];
    float*               out    = (float*)d_out;

    float *fused, *yp;
    __nv_bfloat16 *ah, *al, *wqh, *wql, *woh, *wol, *ch, *cl;
    cudaGetSymbolAddress((void**)&fused, g_fused);
    cudaGetSymbolAddress((void**)&yp,    g_y);
    cudaGetSymbolAddress((void**)&ah,  g_ah);
    cudaGetSymbolAddress((void**)&al,  g_al);
    cudaGetSymbolAddress((void**)&wqh, g_wqh);
    cudaGetSymbolAddress((void**)&wql, g_wql);
    cudaGetSymbolAddress((void**)&woh, g_woh);
    cudaGetSymbolAddress((void**)&wol, g_wol);
    cudaGetSymbolAddress((void**)&ch,  g_ch);
    cudaGetSymbolAddress((void**)&cl,  g_cl);

    cudaFuncSetAttribute(attn_mma, cudaFuncAttributeMaxDynamicSharedMemorySize,
                         ASMEM);
    cudaFuncSetAttribute(mma_gemm<1024, 6144, 0>,
                         cudaFuncAttributeMaxDynamicSharedMemorySize, GSMEM);
    cudaFuncSetAttribute(mma_gemm<3072, 1024, 1>,
                         cudaFuncAttributeMaxDynamicSharedMemorySize, GSMEM);

    mask_detect_kernel<<<1, 256>>>(mask);

    /* bf16x2-split conversions */
    conv_split<<<(ROWS*HID/4 + 255)/256, 256>>>(hidden, ah, al, ROWS*HID/4);
    conv_split_T<<<dim3(N6/32, HID/32), 256>>>(Wqkvu, wqh, wql, HID, N6);
    conv_split_T<<<dim3(HID/32, N3/32), 256>>>(Wout, woh, wol, N3, HID);

    /* fused QKVU GEMM: silu + gate write + v/q/k split + RoPE, all in epi */
    mma_gemm<1024, 6144, 0><<<dim3(48, 32), 256, GSMEM>>>(ah, al, wqh, wql,
                                                          fused, nullptr, nullptr);

    /* tensor-core 3-way attention -> g_ch/g_cl (gated, pre-split) */
    attn_mma<<<dim3(SEQ/64, NHEAD, BATCH), 512, ASMEM>>>(mask, bias, ch, cl);

    /* y = comb @ W_out + b_out + hidden */
    mma_gemm<3072, 1024, 1><<<dim3(8, 32), 256, GSMEM>>>(ch, cl, woh, wol,
                                                         yp, bout, hidden);

    rms_kernel<<<ROWS, 256>>>(yp, rmsw, out);
}

// round 12
// speedup vs baseline: 1.3526x; 1.3526x over previous
#include <cuda_runtime.h>
#include <cuda_fp16.h>
#include <cstdint>
#include <math.h>

#define SEQ   2048
#define BATCH 2
#define HID   1024
#define NHEAD 8
#define HDIM  128
#define ROWS  (BATCH*SEQ)   /* 4096 */
#define N6    (6*HID)       /* 6144 */
#define N3    (3*HID)       /* 3072 */

/* ---------------- scratch (device globals; no allocation allowed) ------- */
__device__ float g_fused[(size_t)ROWS*N6];   /* gate section fp32 (cols<3072) */
__device__ float g_y[(size_t)ROWS*HID];
__device__ int   g_mask_int;

/* fp16 2-pass split: A-side split (hi+lo), B-side single fp16 */
__device__ __half g_ah[(size_t)ROWS*HID];          /* hidden hi */
__device__ __half g_al[(size_t)ROWS*HID];          /* hidden lo */
__device__ __half g_wqh[(size_t)N6*HID];           /* W_qkvu^T single */
__device__ __half g_woh[(size_t)HID*N3];           /* W_out^T  single */
__device__ __half g_ch[(size_t)ROWS*N3];           /* gated attn out hi */
__device__ __half g_cl[(size_t)ROWS*N3];           /* gated attn out lo */

/* attention: q split, k/v single; layout [row][h*128+d] */
__device__ __half g_qh[(size_t)ROWS*HID],  g_ql[(size_t)ROWS*HID];
__device__ __half g_qrh[(size_t)ROWS*HID], g_qrl[(size_t)ROWS*HID];
__device__ __half g_kh[(size_t)ROWS*HID];
__device__ __half g_krh[(size_t)ROWS*HID];
__device__ __half g_vh[(size_t)ROWS*HID];

/* ================= helpers ============================================= */
__device__ __forceinline__ uint32_t smem_u32(const void* p) {
    uint32_t a;
    asm("{ .reg .u64 t; cvta.to.shared.u64 t, %1; cvt.u32.u64 %0, t; }"
        : "=r"(a) : "l"(p));
    return a;
}
__device__ __forceinline__ void cp16(uint32_t saddr, const void* g) {
    asm volatile("cp.async.cg.shared.global [%0], [%1], 16;"
                 :: "r"(saddr), "l"(g));
}
#define CP_COMMIT() asm volatile("cp.async.commit_group;" ::: "memory")
#define CP_WAIT0()  asm volatile("cp.async.wait_group 0;" ::: "memory")
#define CP_WAIT1()  asm volatile("cp.async.wait_group 1;" ::: "memory")

__device__ __forceinline__ void ldm_x4(uint32_t* r, uint32_t addr) {
    asm volatile("ldmatrix.sync.aligned.m8n8.x4.shared.b16 {%0,%1,%2,%3}, [%4];"
                 : "=r"(r[0]), "=r"(r[1]), "=r"(r[2]), "=r"(r[3]) : "r"(addr));
}
__device__ __forceinline__ void ldm_x2(uint32_t* r, uint32_t addr) {
    asm volatile("ldmatrix.sync.aligned.m8n8.x2.shared.b16 {%0,%1}, [%2];"
                 : "=r"(r[0]), "=r"(r[1]) : "r"(addr));
}
__device__ __forceinline__ void ldm_x4_t(uint32_t* r, uint32_t addr) {
    asm volatile("ldmatrix.sync.aligned.m8n8.x4.trans.shared.b16 {%0,%1,%2,%3}, [%4];"
                 : "=r"(r[0]), "=r"(r[1]), "=r"(r[2]), "=r"(r[3]) : "r"(addr));
}
__device__ __forceinline__ void mma_f16(float* d,
                                        const uint32_t* a,
                                        uint32_t b0, uint32_t b1) {
    asm volatile("mma.sync.aligned.m16n8k16.row.col.f32.f16.f16.f32 "
                 "{%0,%1,%2,%3},{%4,%5,%6,%7},{%8,%9},{%0,%1,%2,%3};"
                 : "+f"(d[0]), "+f"(d[1]), "+f"(d[2]), "+f"(d[3])
                 : "r"(a[0]), "r"(a[1]), "r"(a[2]), "r"(a[3]), "r"(b0), "r"(b1));
}
__device__ __forceinline__ void split_pair(float x0, float x1,
                                           __half* ph, __half* pl) {
    __half h0 = __float2half_rn(x0), h1 = __float2half_rn(x1);
    *(__half2*)ph = __halves2half2(h0, h1);
    *(__half2*)pl = __halves2half2(__float2half_rn(x0 - __half2float(h0)),
                                   __float2half_rn(x1 - __half2float(h1)));
}

/* ========== cp.async double-buffered fp16 2-pass GEMM: C = A @ B^T ===== */
/* A split (hi+lo), B single.  Block 128x128, BK=32, 8 warps (2m x 4n).    */
/* EPI 0: QKVU epilogue (silu + gate/v/q/k routing + fused RoPE).          */
/* EPI 1: + bias + resid -> fp32 C.                                        */
#define TSTR   40
#define GTILE  10240                    /* 128*TSTR*2 bytes */
#define GSTAGE (3*GTILE)                /* AH AL BH */
#define GSMEM  (2*GSTAGE)               /* 61440 */

template<int KDIM, int NDIM, int EPI>
__global__ __launch_bounds__(256)
void mma_gemm(const __half* __restrict__ Ah, const __half* __restrict__ Al,
              const __half* __restrict__ Bh,
              float* __restrict__ C,
              const float* __restrict__ bias, const float* __restrict__ resid)
{
    extern __shared__ char dsm[];
    const uint32_t sb = smem_u32(dsm);

    const int tid  = threadIdx.x;
    const int lane = tid & 31, wid = tid >> 5;
    const int wm = wid >> 2, wn = wid & 3;
    const int m0 = blockIdx.y * 128, n0 = blockIdx.x * 128;

    const int a_r = lane & 15;
    const int a_c = (lane >> 4) * 8;
    const int b_r = (lane & 7) + ((lane >> 4) & 1) * 8;
    const int b_c = ((lane >> 3) & 1) * 8;

    float acc[4][4][4];
#pragma unroll
    for (int i = 0; i < 4; i++)
#pragma unroll
        for (int j = 0; j < 4; j++)
#pragma unroll
            for (int r = 0; r < 4; r++) acc[i][j][r] = 0.f;

    const int NC = KDIM / 32;

    /* prefetch chunk 0 */
    {
        uint32_t bs = sb;
#pragma unroll
        for (int i = 0; i < 2; i++) {
            int idx = tid + 256 * i;
            int row = idx >> 2, seg = (idx & 3) << 3;
            size_t ga = (size_t)(m0 + row) * KDIM + seg;
            size_t gb = (size_t)(n0 + row) * KDIM + seg;
            uint32_t so = (uint32_t)(row * TSTR + seg) * 2;
            cp16(bs + 0*GTILE + so, Ah + ga);
            cp16(bs + 1*GTILE + so, Al + ga);
            cp16(bs + 2*GTILE + so, Bh + gb);
        }
        CP_COMMIT();
    }

    for (int ic = 0; ic < NC; ic++) {
        if (ic + 1 < NC) {
            int kc = (ic + 1) * 32;
            uint32_t bs = sb + ((ic + 1) & 1) * GSTAGE;
#pragma unroll
            for (int i = 0; i < 2; i++) {
                int idx = tid + 256 * i;
                int row = idx >> 2, seg = (idx & 3) << 3;
                size_t ga = (size_t)(m0 + row) * KDIM + kc + seg;
                size_t gb = (size_t)(n0 + row) * KDIM + kc + seg;
                uint32_t so = (uint32_t)(row * TSTR + seg) * 2;
                cp16(bs + 0*GTILE + so, Ah + ga);
                cp16(bs + 1*GTILE + so, Al + ga);
                cp16(bs + 2*GTILE + so, Bh + gb);
            }
            CP_COMMIT();
            CP_WAIT1();
        } else {
            CP_WAIT0();
        }
        __syncthreads();

        const uint32_t bs = sb + (ic & 1) * GSTAGE;
        const uint32_t uAh = bs, uAl = bs + GTILE, uBh = bs + 2*GTILE;

#pragma unroll
        for (int k0 = 0; k0 < 32; k0 += 16) {
            uint32_t fAh[4][4], fAl[4][4], fB[2][4];
#pragma unroll
            for (int mt = 0; mt < 4; mt++)
                ldm_x4(fAh[mt], uAh + (uint32_t)((wm*64 + mt*16 + a_r) * TSTR + k0 + a_c) * 2);
#pragma unroll
            for (int bp = 0; bp < 2; bp++)
                ldm_x4(fB[bp], uBh + (uint32_t)((wn*32 + bp*16 + b_r) * TSTR + k0 + b_c) * 2);
#pragma unroll
            for (int mt = 0; mt < 4; mt++)
#pragma unroll
                for (int nt = 0; nt < 4; nt++)
                    mma_f16(acc[mt][nt], fAh[mt],
                            fB[nt>>1][(nt&1)*2], fB[nt>>1][(nt&1)*2+1]);
#pragma unroll
            for (int mt = 0; mt < 4; mt++)
                ldm_x4(fAl[mt], uAl + (uint32_t)((wm*64 + mt*16 + a_r) * TSTR + k0 + a_c) * 2);
#pragma unroll
            for (int mt = 0; mt < 4; mt++)
#pragma unroll
                for (int nt = 0; nt < 4; nt++)
                    mma_f16(acc[mt][nt], fAl[mt],
                            fB[nt>>1][(nt&1)*2], fB[nt>>1][(nt&1)*2+1]);
        }
        __syncthreads();
    }

    const int er = lane >> 2, ec = (lane & 3) * 2;
#pragma unroll
    for (int mt = 0; mt < 4; mt++) {
#pragma unroll
        for (int nt = 0; nt < 4; nt++) {
            int col = n0 + wn*32 + nt*8 + ec;
#pragma unroll
            for (int half = 0; half < 2; half++) {
                size_t row = (size_t)(m0 + wm*64 + mt*16 + er + half*8);
                float v0 = acc[mt][nt][half*2 + 0];
                float v1 = acc[mt][nt][half*2 + 1];
                if (EPI == 0) {
                    float s0 = v0 / (1.f + expf(-v0));
                    float s1 = v1 / (1.f + expf(-v1));
                    if (col < 3*HID) {
                        float2 o; o.x = s0; o.y = s1;
                        *(float2*)&C[row * NDIM + col] = o;
                    } else if (col < 4*HID) {
                        int d = col - 3*HID;
                        *(__half2*)&g_vh[row*HID + d] =
                            __halves2half2(__float2half_rn(s0), __float2half_rn(s1));
                    } else {
                        /* q or k: fused RoPE on (2i, 2i+1) pair */
                        int d = col & (HID - 1);
                        int i = (d & 127) >> 1;
                        float ang = (float)(row & (SEQ - 1))
                                  / powf(10000.f, (float)i / 64.f);
                        float sn, cs;
                        sincosf(ang, &sn, &cs);
                        float r0 = s0 * cs - s1 * sn;
                        float r1 = s1 * cs + s0 * sn;
                        size_t o = row * HID + d;
                        if (col < 5*HID) {
                            split_pair(s0, s1, g_qh  + o, g_ql  + o);
                            split_pair(r0, r1, g_qrh + o, g_qrl + o);
                        } else {
                            *(__half2*)&g_kh[o] =
                                __halves2half2(__float2half_rn(s0), __float2half_rn(s1));
                            *(__half2*)&g_krh[o] =
                                __halves2half2(__float2half_rn(r0), __float2half_rn(r1));
                        }
                    }
                } else {
                    size_t rb = row * NDIM + col;
                    float2 o;
                    o.x = v0 + bias[col+0] + resid[rb+0];
                    o.y = v1 + bias[col+1] + resid[rb+1];
                    *(float2*)&C[row * NDIM + col] = o;
                }
            }
        }
    }
}

/* ============ conversions ============================================== */
__global__ __launch_bounds__(256)
void conv_split(const float* __restrict__ A, __half* __restrict__ H,
                __half* __restrict__ L, int n4)
{
    int i = blockIdx.x * 256 + threadIdx.x;
    if (i >= n4) return;
    float4 v = *(const float4*)(A + (size_t)i * 4);
    split_pair(v.x, v.y, H + (size_t)i*4,     L + (size_t)i*4);
    split_pair(v.z, v.w, H + (size_t)i*4 + 2, L + (size_t)i*4 + 2);
}

/* W [K][N] row-major -> T [N][K] single fp16 */
__global__ __launch_bounds__(256)
void conv_T(const float* __restrict__ W, __half* __restrict__ Th, int K, int N)
{
    __shared__ float t[32][33];
    int kb = blockIdx.y * 32, nb = blockIdx.x * 32;
    int tx = threadIdx.x & 31, ty = threadIdx.x >> 5;
#pragma unroll
    for (int i = 0; i < 4; i++) {
        int k = ty + 8 * i;
        t[k][tx] = W[(size_t)(kb + k) * N + nb + tx];
    }
    __syncthreads();
#pragma unroll
    for (int i = 0; i < 4; i++) {
        int n = ty + 8 * i;
        Th[(size_t)(nb + n) * K + kb + tx] = __float2half_rn(t[tx][n]);
    }
}

/* ---------------- mask dtype detector ---------------------------------- */
__global__ void mask_detect_kernel(const unsigned char* __restrict__ mask)
{
    __shared__ int cnt;
    if (threadIdx.x == 0) cnt = 0;
    __syncthreads();
    int c = 0;
    for (int i = threadIdx.x; i < 16384; i += 256) c += (mask[i] != 0);
    atomicAdd(&cnt, c);
    __syncthreads();
    if (threadIdx.x == 0) g_mask_int = (cnt < 4096) ? 1 : 0;
}

/* ---------------- tensor-core 3-way attention (fp16 2-pass) ------------ */
#define KSTR 136   /* K/V/Q smem row stride (halves): 128 + 8 */
#define SSTR 40    /* S smem row stride: 32 + 8 */
#define KTILE 8704 /* 32*KSTR*2 */

/* smem byte offsets */
#define O_QH   0
#define O_QL   17408
#define O_QRH  34816
#define O_QRL  52224
#define O_KV   69632
#define KV_STAGE (3*KTILE)      /* kh, krh, vh = 26112 */
#define O_SRH  121856
#define O_SRL  126976
#define O_STH  132096
#define O_STL  137216
#define O_SPH  142336
#define O_SPL  147456
#define O_MK   152576
#define ASMEM  154624

__global__ __launch_bounds__(512)
void attn_mma(const unsigned char* __restrict__ mask,
              const float* __restrict__ bias,
              __half* __restrict__ ch, __half* __restrict__ cl)
{
    extern __shared__ char sm[];
    const uint32_t sb = smem_u32(sm);
    unsigned char* MKb = (unsigned char*)(sm + O_MK);

    const int b = blockIdx.z, h = blockIdx.y, q0 = blockIdx.x * 64;
    const int tid = threadIdx.x, lane = tid & 31, wid = tid >> 5;
    const int wq = wid >> 2, wx = wid & 3;     /* 16 warps: 4 q-sub x 4 x */
    const int mint = g_mask_int;
    const float inv_s = 1.0f / (float)SEQ;

    const int a_r = lane & 15, a_c = (lane >> 4) * 8;
    const int b_r = lane & 7,  b_c = ((lane >> 3) & 1) * 8;
    const int er  = lane >> 2, ec  = (lane & 3) * 2;

    /* persistent Q tiles: 64 rows x 128 cols, 1024 chunks per tile */
#pragma unroll
    for (int i = 0; i < 2; i++) {
        int c = tid + 512 * i;
        int row = c >> 4, seg = (c & 15) * 8;
        size_t g = (size_t)(b * SEQ + q0 + row) * HID + h * 128 + seg;
        int so = (row * KSTR + seg) * 2;
        *(uint4*)(sm + O_QH  + so) = *(const uint4*)&g_qh[g];
        *(uint4*)(sm + O_QL  + so) = *(const uint4*)&g_ql[g];
        *(uint4*)(sm + O_QRH + so) = *(const uint4*)&g_qrh[g];
        *(uint4*)(sm + O_QRL + so) = *(const uint4*)&g_qrl[g];
    }

    float accB[3][4][4];
#pragma unroll
    for (int s = 0; s < 3; s++)
#pragma unroll
        for (int j = 0; j < 4; j++)
#pragma unroll
            for (int r = 0; r < 4; r++) accB[s][j][r] = 0.f;

    const int NIT = SEQ / 32;

    /* prefetch KV tiles for m-iter 0 (512 chunks, one per thread) */
    {
        uint32_t bs = sb + O_KV;
        int row = tid >> 4, seg = (tid & 15) * 8;
        size_t g = (size_t)(b * SEQ + row) * HID + h * 128 + seg;
        uint32_t so = (uint32_t)(row * KSTR + seg) * 2;
        cp16(bs + 0*KTILE + so, g_kh  + g);
        cp16(bs + 1*KTILE + so, g_krh + g);
        cp16(bs + 2*KTILE + so, g_vh  + g);
        CP_COMMIT();
    }
    __syncthreads();   /* Q tiles visible */

    for (int it = 0; it < NIT; it++) {
        const int m0 = it * 32;

        /* prefetch next m-tile */
        if (it + 1 < NIT) {
            uint32_t bs = sb + O_KV + ((it + 1) & 1) * KV_STAGE;
            int mn = (it + 1) * 32;
            int row = tid >> 4, seg = (tid & 15) * 8;
            size_t g = (size_t)(b * SEQ + mn + row) * HID + h * 128 + seg;
            uint32_t so = (uint32_t)(row * KSTR + seg) * 2;
            cp16(bs + 0*KTILE + so, g_kh  + g);
            cp16(bs + 1*KTILE + so, g_krh + g);
            cp16(bs + 2*KTILE + so, g_vh  + g);
            CP_COMMIT();
        }

        /* mask tile + ts scores: 64x32 entries, 4 per thread */
        {
            int n = tid >> 3, seg = (tid & 7) * 4;
            size_t gi = ((size_t)b * SEQ + q0 + n) * SEQ + m0 + seg;
            float4 bv = *(const float4*)&bias[gi];
            float mf[4];
            if (mint) {
                int4 mi = *(const int4*)&((const int*)mask)[gi];
                mf[0]=mi.x?1.f:0.f; mf[1]=mi.y?1.f:0.f;
                mf[2]=mi.z?1.f:0.f; mf[3]=mi.w?1.f:0.f;
            } else {
                uchar4 mu = *(const uchar4*)&mask[gi];
                mf[0]=mu.x?1.f:0.f; mf[1]=mu.y?1.f:0.f;
                mf[2]=mu.z?1.f:0.f; mf[3]=mu.w?1.f:0.f;
            }
#pragma unroll
            for (int j = 0; j < 4; j++) MKb[n * 32 + seg + j] = (unsigned char)mf[j];
            __half* TH = (__half*)(sm + O_STH);
            __half* TL = (__half*)(sm + O_STL);
            split_pair(mf[0] * bv.x, mf[1] * bv.y,
                       TH + n * SSTR + seg,     TL + n * SSTR + seg);
            split_pair(mf[2] * bv.z, mf[3] * bv.w,
                       TH + n * SSTR + seg + 2, TL + n * SSTR + seg + 2);
        }

        if (it + 1 < NIT) { CP_WAIT1(); } else { CP_WAIT0(); }
        __syncthreads();   /* KV(it) + MK/ST visible */

        const uint32_t kb = sb + O_KV + (it & 1) * KV_STAGE;

        /* phase A: each warp one 16x8 tile; plain (v=0), rope (v=1) */
#pragma unroll
        for (int v = 0; v < 2; v++) {
            const uint32_t uQh = sb + (v ? O_QRH : O_QH);
            const uint32_t uQl = sb + (v ? O_QRL : O_QL);
            const uint32_t uKh = kb + (v ? KTILE : 0);
            float acc[4];
#pragma unroll
            for (int r = 0; r < 4; r++) acc[r] = 0.f;

#pragma unroll
            for (int k16 = 0; k16 < 8; k16++) {
                int k0 = k16 * 16;
                uint32_t fAh[4], fAl[4], fBh[2];
                ldm_x4(fAh, uQh + (uint32_t)((wq*16 + a_r) * KSTR + k0 + a_c) * 2);
                ldm_x4(fAl, uQl + (uint32_t)((wq*16 + a_r) * KSTR + k0 + a_c) * 2);
                ldm_x2(fBh, uKh + (uint32_t)((wx*8 + b_r) * KSTR + k0 + b_c) * 2);
                mma_f16(acc, fAh, fBh[0], fBh[1]);
                mma_f16(acc, fAl, fBh[0], fBh[1]);
            }
            __half* SH = (__half*)(sm + (v ? O_SRH : O_SPH));
            __half* SL = (__half*)(sm + (v ? O_SRL : O_SPL));
#pragma unroll
            for (int half = 0; half < 2; half++) {
                int r = wq*16 + er + half*8;
                int c = wx*8 + ec;
                float f0 = (float)MKb[r*32 + c];
                float f1 = (float)MKb[r*32 + c + 1];
                float s0 = f0 * fmaxf(acc[half*2 + 0], 0.f) * inv_s;
                float s1 = f1 * fmaxf(acc[half*2 + 1], 0.f) * inv_s;
                split_pair(s0, s1, SH + r*SSTR + c, SL + r*SSTR + c);
            }
        }
        __syncthreads();

        /* phase B: warp (wq, wx): rows wq*16, cols wx*32, all 3 secs */
        const uint32_t uSH[3] = {sb + O_SRH, sb + O_STH, sb + O_SPH};
        const uint32_t uSL[3] = {sb + O_SRL, sb + O_STL, sb + O_SPL};
        const uint32_t uVh = kb + 2*KTILE;
#pragma unroll
        for (int k16 = 0; k16 < 2; k16++) {
            int k0 = k16 * 16;
            uint32_t fVh[2][4];
#pragma unroll
            for (int dh = 0; dh < 2; dh++)
                ldm_x4_t(fVh[dh], uVh + (uint32_t)((k0 + a_r) * KSTR + wx*32 + dh*16 + a_c) * 2);
#pragma unroll
            for (int sec = 0; sec < 3; sec++) {
                uint32_t fSh[4], fSl[4];
                ldm_x4(fSh, uSH[sec] + (uint32_t)((wq*16 + a_r) * SSTR + k0 + a_c) * 2);
                ldm_x4(fSl, uSL[sec] + (uint32_t)((wq*16 + a_r) * SSTR + k0 + a_c) * 2);
#pragma unroll
                for (int j = 0; j < 4; j++) {
                    uint32_t bh0 = fVh[j>>1][(j&1)*2], bh1 = fVh[j>>1][(j&1)*2+1];
                    mma_f16(accB[sec][j], fSh, bh0, bh1);
                    mma_f16(accB[sec][j], fSl, bh0, bh1);
                }
            }
        }
        __syncthreads();   /* all tiles consumed before next prefetch */
    }

    /* final epilogue: * gate, fp16-split into ch/cl                       */
#pragma unroll
    for (int sec = 0; sec < 3; sec++) {
#pragma unroll
        for (int j = 0; j < 4; j++) {
#pragma unroll
            for (int half = 0; half < 2; half++) {
                int rl = wq*16 + er + half*8;
                size_t grow = (size_t)(b * SEQ + q0 + rl);
                int d = wx*32 + j*8 + ec;
                int cx = h*384 + sec*128 + d;
                float2 g = *(const float2*)&g_fused[grow * N6 + cx];
                float o0 = accB[sec][j][half*2 + 0] * g.x;
                float o1 = accB[sec][j][half*2 + 1] * g.y;
                split_pair(o0, o1, ch + grow * N3 + cx, cl + grow * N3 + cx);
            }
        }
    }
}

/* ---------------- RMSNorm --------------------------------------------- */
__global__ __launch_bounds__(256)
void rms_kernel(const float* __restrict__ y, const float* __restrict__ w,
                float* __restrict__ out)
{
    __shared__ float sh[8];
    __shared__ float tot;
    int row = blockIdx.x;
    const float* yr = y + (size_t)row * HID;
    float ss = 0.f;
    for (int i = threadIdx.x; i < HID; i += 256) {
        float v = yr[i];
        ss = fmaf(v, v, ss);
    }
#pragma unroll
    for (int o = 16; o > 0; o >>= 1) ss += __shfl_down_sync(0xffffffffu, ss, o);
    if ((threadIdx.x & 31) == 0) sh[threadIdx.x >> 5] = ss;
    __syncthreads();
    if (threadIdx.x == 0) {
        float t = 0.f;
#pragma unroll
        for (int i = 0; i < 8; i++) t += sh[i];
        tot = rsqrtf(t / (float)HID + 1e-6f);
    }
    __syncthreads();
    float r = tot;
    for (int i = threadIdx.x; i < HID; i += 256)
        out[(size_t)row * HID + i] = yr[i] * r * w[i];
}

/* ---------------- launch ----------------------------------------------- */
extern "C" void kernel_launch(void* const* d_in, const int* in_sizes, int n_in,
                              void* d_out, int out_size)
{
    const float*         hidden = (const float*)d_in[0];
    const unsigned char* mask   = (const unsigned char*)d_in[1];
    const float*         bias   = (const float*)d_in[2];
    const float*         Wqkvu  = (const float*)d_in[3];
    const float*         Wout   = (const float*)d_in[4];
    const float*         bout   = (const float*)d_in[5];
    const float*         rmsw   = (const float*)d_in[6];
    float*               out    = (float*)d_out;

    float *fused, *yp;
    __half *ah, *al, *wqh, *woh, *ch, *cl;
    cudaGetSymbolAddress((void**)&fused, g_fused);
    cudaGetSymbolAddress((void**)&yp,    g_y);
    cudaGetSymbolAddress((void**)&ah,  g_ah);
    cudaGetSymbolAddress((void**)&al,  g_al);
    cudaGetSymbolAddress((void**)&wqh, g_wqh);
    cudaGetSymbolAddress((void**)&woh, g_woh);
    cudaGetSymbolAddress((void**)&ch,  g_ch);
    cudaGetSymbolAddress((void**)&cl,  g_cl);

    cudaFuncSetAttribute(attn_mma, cudaFuncAttributeMaxDynamicSharedMemorySize,
                         ASMEM);
    cudaFuncSetAttribute(mma_gemm<1024, 6144, 0>,
                         cudaFuncAttributeMaxDynamicSharedMemorySize, GSMEM);
    cudaFuncSetAttribute(mma_gemm<3072, 1024, 1>,
                         cudaFuncAttributeMaxDynamicSharedMemorySize, GSMEM);

    mask_detect_kernel<<<1, 256>>>(mask);

    /* conversions: hidden split; weights single fp16 */
    conv_split<<<(ROWS*HID/4 + 255)/256, 256>>>(hidden, ah, al, ROWS*HID/4);
    conv_T<<<dim3(N6/32, HID/32), 256>>>(Wqkvu, wqh, HID, N6);
    conv_T<<<dim3(HID/32, N3/32), 256>>>(Wout, woh, N3, HID);

    /* fused QKVU GEMM: silu + gate write + v/q/k routing + RoPE in epi */
    mma_gemm<1024, 6144, 0><<<dim3(48, 32), 256, GSMEM>>>(ah, al, wqh,
                                                          fused, nullptr, nullptr);

    /* tensor-core 3-way attention -> g_ch/g_cl (gated, pre-split) */
    attn_mma<<<dim3(SEQ/64, NHEAD, BATCH), 512, ASMEM>>>(mask, bias, ch, cl);

    /* y = comb @ W_out + b_out + hidden */
    mma_gemm<3072, 1024, 1><<<dim3(8, 32), 256, GSMEM>>>(ch, cl, woh,
                                                         yp, bout, hidden);

    rms_kernel<<<ROWS, 256>>>(yp, rmsw, out);
}

// round 13
// speedup vs baseline: 2.0464x; 1.5130x over previous
#include <cuda_runtime.h>
#include <cuda_fp16.h>
#include <cstdint>
#include <math.h>

#define SEQ   2048
#define BATCH 2
#define HID   1024
#define NHEAD 8
#define HDIM  128
#define ROWS  (BATCH*SEQ)   /* 4096 */
#define N6    (6*HID)       /* 6144 */
#define N3    (3*HID)       /* 3072 */

/* ---------------- scratch (device globals; no allocation allowed) ------- */
__device__ float g_fused[(size_t)ROWS*N6];   /* gate section fp32 (cols<3072) */
__device__ float g_y[(size_t)ROWS*HID];
__device__ int   g_mask_int;

/* single-fp16 operands everywhere */
__device__ __half g_ah[(size_t)ROWS*HID];          /* hidden fp16 */
__device__ __half g_wqh[(size_t)N6*HID];           /* W_qkvu^T */
__device__ __half g_woh[(size_t)HID*N3];           /* W_out^T  */
__device__ __half g_ch[(size_t)ROWS*N3];           /* gated attn out */

/* attention operands, layout [row][h*128+d] */
__device__ __half g_qh[(size_t)ROWS*HID];
__device__ __half g_qrh[(size_t)ROWS*HID];
__device__ __half g_kh[(size_t)ROWS*HID];
__device__ __half g_krh[(size_t)ROWS*HID];
__device__ __half g_vh[(size_t)ROWS*HID];

/* ================= helpers ============================================= */
__device__ __forceinline__ uint32_t smem_u32(const void* p) {
    uint32_t a;
    asm("{ .reg .u64 t; cvta.to.shared.u64 t, %1; cvt.u32.u64 %0, t; }"
        : "=r"(a) : "l"(p));
    return a;
}
__device__ __forceinline__ void cp16(uint32_t saddr, const void* g) {
    asm volatile("cp.async.cg.shared.global [%0], [%1], 16;"
                 :: "r"(saddr), "l"(g));
}
#define CP_COMMIT() asm volatile("cp.async.commit_group;" ::: "memory")
#define CP_WAIT0()  asm volatile("cp.async.wait_group 0;" ::: "memory")
#define CP_WAIT1()  asm volatile("cp.async.wait_group 1;" ::: "memory")

__device__ __forceinline__ void ldm_x4(uint32_t* r, uint32_t addr) {
    asm volatile("ldmatrix.sync.aligned.m8n8.x4.shared.b16 {%0,%1,%2,%3}, [%4];"
                 : "=r"(r[0]), "=r"(r[1]), "=r"(r[2]), "=r"(r[3]) : "r"(addr));
}
__device__ __forceinline__ void ldm_x2(uint32_t* r, uint32_t addr) {
    asm volatile("ldmatrix.sync.aligned.m8n8.x2.shared.b16 {%0,%1}, [%2];"
                 : "=r"(r[0]), "=r"(r[1]) : "r"(addr));
}
__device__ __forceinline__ void ldm_x4_t(uint32_t* r, uint32_t addr) {
    asm volatile("ldmatrix.sync.aligned.m8n8.x4.trans.shared.b16 {%0,%1,%2,%3}, [%4];"
                 : "=r"(r[0]), "=r"(r[1]), "=r"(r[2]), "=r"(r[3]) : "r"(addr));
}
__device__ __forceinline__ void mma_f16(float* d,
                                        const uint32_t* a,
                                        uint32_t b0, uint32_t b1) {
    asm volatile("mma.sync.aligned.m16n8k16.row.col.f32.f16.f16.f32 "
                 "{%0,%1,%2,%3},{%4,%5,%6,%7},{%8,%9},{%0,%1,%2,%3};"
                 : "+f"(d[0]), "+f"(d[1]), "+f"(d[2]), "+f"(d[3])
                 : "r"(a[0]), "r"(a[1]), "r"(a[2]), "r"(a[3]), "r"(b0), "r"(b1));
}
__device__ __forceinline__ void st_h2(__half* p, float x0, float x1) {
    *(__half2*)p = __halves2half2(__float2half_rn(x0), __float2half_rn(x1));
}

/* ========== cp.async double-buffered fp16 GEMM: C = A @ B^T ============ */
/* Single-precision-fp16 operands.  Block 128x128, BK=32, 8 warps (2m x 4n).*/
/* EPI 0: QKVU epilogue (silu + gate/v/q/k routing + fused RoPE).          */
/* EPI 1: + bias + resid -> fp32 C.                                        */
#define TSTR   40
#define GTILE  10240                    /* 128*TSTR*2 bytes */
#define GSTAGE (2*GTILE)                /* A B */
#define GSMEM  (2*GSTAGE)               /* 40960 */

template<int KDIM, int NDIM, int EPI>
__global__ __launch_bounds__(256)
void mma_gemm(const __half* __restrict__ Ah, const __half* __restrict__ Bh,
              float* __restrict__ C,
              const float* __restrict__ bias, const float* __restrict__ resid)
{
    extern __shared__ char dsm[];
    const uint32_t sb = smem_u32(dsm);

    const int tid  = threadIdx.x;
    const int lane = tid & 31, wid = tid >> 5;
    const int wm = wid >> 2, wn = wid & 3;
    const int m0 = blockIdx.y * 128, n0 = blockIdx.x * 128;

    const int a_r = lane & 15;
    const int a_c = (lane >> 4) * 8;
    const int b_r = (lane & 7) + ((lane >> 4) & 1) * 8;
    const int b_c = ((lane >> 3) & 1) * 8;

    float acc[4][4][4];
#pragma unroll
    for (int i = 0; i < 4; i++)
#pragma unroll
        for (int j = 0; j < 4; j++)
#pragma unroll
            for (int r = 0; r < 4; r++) acc[i][j][r] = 0.f;

    const int NC = KDIM / 32;

    /* prefetch chunk 0 */
    {
        uint32_t bs = sb;
#pragma unroll
        for (int i = 0; i < 2; i++) {
            int idx = tid + 256 * i;
            int row = idx >> 2, seg = (idx & 3) << 3;
            size_t ga = (size_t)(m0 + row) * KDIM + seg;
            size_t gb = (size_t)(n0 + row) * KDIM + seg;
            uint32_t so = (uint32_t)(row * TSTR + seg) * 2;
            cp16(bs + 0*GTILE + so, Ah + ga);
            cp16(bs + 1*GTILE + so, Bh + gb);
        }
        CP_COMMIT();
    }

    for (int ic = 0; ic < NC; ic++) {
        if (ic + 1 < NC) {
            int kc = (ic + 1) * 32;
            uint32_t bs = sb + ((ic + 1) & 1) * GSTAGE;
#pragma unroll
            for (int i = 0; i < 2; i++) {
                int idx = tid + 256 * i;
                int row = idx >> 2, seg = (idx & 3) << 3;
                size_t ga = (size_t)(m0 + row) * KDIM + kc + seg;
                size_t gb = (size_t)(n0 + row) * KDIM + kc + seg;
                uint32_t so = (uint32_t)(row * TSTR + seg) * 2;
                cp16(bs + 0*GTILE + so, Ah + ga);
                cp16(bs + 1*GTILE + so, Bh + gb);
            }
            CP_COMMIT();
            CP_WAIT1();
        } else {
            CP_WAIT0();
        }
        __syncthreads();

        const uint32_t bs = sb + (ic & 1) * GSTAGE;
        const uint32_t uAh = bs, uBh = bs + GTILE;

#pragma unroll
        for (int k0 = 0; k0 < 32; k0 += 16) {
            uint32_t fAh[4][4], fB[2][4];
#pragma unroll
            for (int mt = 0; mt < 4; mt++)
                ldm_x4(fAh[mt], uAh + (uint32_t)((wm*64 + mt*16 + a_r) * TSTR + k0 + a_c) * 2);
#pragma unroll
            for (int bp = 0; bp < 2; bp++)
                ldm_x4(fB[bp], uBh + (uint32_t)((wn*32 + bp*16 + b_r) * TSTR + k0 + b_c) * 2);
#pragma unroll
            for (int mt = 0; mt < 4; mt++)
#pragma unroll
                for (int nt = 0; nt < 4; nt++)
                    mma_f16(acc[mt][nt], fAh[mt],
                            fB[nt>>1][(nt&1)*2], fB[nt>>1][(nt&1)*2+1]);
        }
        __syncthreads();
    }

    const int er = lane >> 2, ec = (lane & 3) * 2;
#pragma unroll
    for (int mt = 0; mt < 4; mt++) {
#pragma unroll
        for (int nt = 0; nt < 4; nt++) {
            int col = n0 + wn*32 + nt*8 + ec;
#pragma unroll
            for (int half = 0; half < 2; half++) {
                size_t row = (size_t)(m0 + wm*64 + mt*16 + er + half*8);
                float v0 = acc[mt][nt][half*2 + 0];
                float v1 = acc[mt][nt][half*2 + 1];
                if (EPI == 0) {
                    float s0 = v0 / (1.f + expf(-v0));
                    float s1 = v1 / (1.f + expf(-v1));
                    if (col < 3*HID) {
                        float2 o; o.x = s0; o.y = s1;
                        *(float2*)&C[row * NDIM + col] = o;
                    } else if (col < 4*HID) {
                        int d = col - 3*HID;
                        st_h2(&g_vh[row*HID + d], s0, s1);
                    } else {
                        /* q or k: fused RoPE on (2i, 2i+1) pair */
                        int d = col & (HID - 1);
                        int i = (d & 127) >> 1;
                        float ang = (float)(row & (SEQ - 1))
                                  / powf(10000.f, (float)i / 64.f);
                        float sn, cs;
                        sincosf(ang, &sn, &cs);
                        float r0 = s0 * cs - s1 * sn;
                        float r1 = s1 * cs + s0 * sn;
                        size_t o = row * HID + d;
                        if (col < 5*HID) {
                            st_h2(&g_qh[o],  s0, s1);
                            st_h2(&g_qrh[o], r0, r1);
                        } else {
                            st_h2(&g_kh[o],  s0, s1);
                            st_h2(&g_krh[o], r0, r1);
                        }
                    }
                } else {
                    size_t rb = row * NDIM + col;
                    float2 o;
                    o.x = v0 + bias[col+0] + resid[rb+0];
                    o.y = v1 + bias[col+1] + resid[rb+1];
                    *(float2*)&C[row * NDIM + col] = o;
                }
            }
        }
    }
}

/* ============ conversions ============================================== */
__global__ __launch_bounds__(256)
void conv_h(const float* __restrict__ A, __half* __restrict__ H, int n4)
{
    int i = blockIdx.x * 256 + threadIdx.x;
    if (i >= n4) return;
    float4 v = *(const float4*)(A + (size_t)i * 4);
    st_h2(H + (size_t)i*4,     v.x, v.y);
    st_h2(H + (size_t)i*4 + 2, v.z, v.w);
}

/* W [K][N] row-major -> T [N][K] fp16 */
__global__ __launch_bounds__(256)
void conv_T(const float* __restrict__ W, __half* __restrict__ Th, int K, int N)
{
    __shared__ float t[32][33];
    int kb = blockIdx.y * 32, nb = blockIdx.x * 32;
    int tx = threadIdx.x & 31, ty = threadIdx.x >> 5;
#pragma unroll
    for (int i = 0; i < 4; i++) {
        int k = ty + 8 * i;
        t[k][tx] = W[(size_t)(kb + k) * N + nb + tx];
    }
    __syncthreads();
#pragma unroll
    for (int i = 0; i < 4; i++) {
        int n = ty + 8 * i;
        Th[(size_t)(nb + n) * K + kb + tx] = __float2half_rn(t[tx][n]);
    }
}

/* ---------------- mask dtype detector ---------------------------------- */
__global__ void mask_detect_kernel(const unsigned char* __restrict__ mask)
{
    __shared__ int cnt;
    if (threadIdx.x == 0) cnt = 0;
    __syncthreads();
    int c = 0;
    for (int i = threadIdx.x; i < 16384; i += 256) c += (mask[i] != 0);
    atomicAdd(&cnt, c);
    __syncthreads();
    if (threadIdx.x == 0) g_mask_int = (cnt < 4096) ? 1 : 0;
}

/* ---------------- tensor-core 3-way attention (single fp16) ------------ */
#define KSTR 136   /* K/V/Q smem row stride (halves): 128 + 8 */
#define SSTR 40    /* S smem row stride: 32 + 8 */
#define KTILE 8704 /* 32*KSTR*2 */

/* smem byte offsets */
#define O_QH   0
#define O_QRH  17408
#define O_KV   34816
#define KV_STAGE (3*KTILE)      /* kh, krh, vh = 26112; 2 stages end 87040 */
#define O_SR   87040            /* 64*SSTR*2 = 5120 each */
#define O_ST   92160
#define O_SP   97280
#define O_MK   102400           /* 64*32 = 2048 */
#define ASMEM  104448

__global__ __launch_bounds__(512)
void attn_mma(const unsigned char* __restrict__ mask,
              const float* __restrict__ bias,
              __half* __restrict__ ch)
{
    extern __shared__ char sm[];
    const uint32_t sb = smem_u32(sm);
    unsigned char* MKb = (unsigned char*)(sm + O_MK);

    const int b = blockIdx.z, h = blockIdx.y, q0 = blockIdx.x * 64;
    const int tid = threadIdx.x, lane = tid & 31, wid = tid >> 5;
    const int wq = wid >> 2, wx = wid & 3;     /* 16 warps: 4 q-sub x 4 x */
    const int mint = g_mask_int;
    const float inv_s = 1.0f / (float)SEQ;

    const int a_r = lane & 15, a_c = (lane >> 4) * 8;
    const int b_r = lane & 7,  b_c = ((lane >> 3) & 1) * 8;
    const int er  = lane >> 2, ec  = (lane & 3) * 2;

    /* persistent Q tiles (q, qr): 64 rows x 128 cols, 1024 chunks each */
#pragma unroll
    for (int i = 0; i < 2; i++) {
        int c = tid + 512 * i;
        int row = c >> 4, seg = (c & 15) * 8;
        size_t g = (size_t)(b * SEQ + q0 + row) * HID + h * 128 + seg;
        int so = (row * KSTR + seg) * 2;
        *(uint4*)(sm + O_QH  + so) = *(const uint4*)&g_qh[g];
        *(uint4*)(sm + O_QRH + so) = *(const uint4*)&g_qrh[g];
    }

    float accB[3][4][4];
#pragma unroll
    for (int s = 0; s < 3; s++)
#pragma unroll
        for (int j = 0; j < 4; j++)
#pragma unroll
            for (int r = 0; r < 4; r++) accB[s][j][r] = 0.f;

    const int NIT = SEQ / 32;

    /* prefetch KV tiles for m-iter 0 (512 chunks, one per thread) */
    {
        uint32_t bs = sb + O_KV;
        int row = tid >> 4, seg = (tid & 15) * 8;
        size_t g = (size_t)(b * SEQ + row) * HID + h * 128 + seg;
        uint32_t so = (uint32_t)(row * KSTR + seg) * 2;
        cp16(bs + 0*KTILE + so, g_kh  + g);
        cp16(bs + 1*KTILE + so, g_krh + g);
        cp16(bs + 2*KTILE + so, g_vh  + g);
        CP_COMMIT();
    }
    __syncthreads();   /* Q tiles visible */

    for (int it = 0; it < NIT; it++) {
        const int m0 = it * 32;

        /* prefetch next m-tile */
        if (it + 1 < NIT) {
            uint32_t bs = sb + O_KV + ((it + 1) & 1) * KV_STAGE;
            int mn = (it + 1) * 32;
            int row = tid >> 4, seg = (tid & 15) * 8;
            size_t g = (size_t)(b * SEQ + mn + row) * HID + h * 128 + seg;
            uint32_t so = (uint32_t)(row * KSTR + seg) * 2;
            cp16(bs + 0*KTILE + so, g_kh  + g);
            cp16(bs + 1*KTILE + so, g_krh + g);
            cp16(bs + 2*KTILE + so, g_vh  + g);
            CP_COMMIT();
        }

        /* mask tile + ts scores: 64x32 entries, 4 per thread */
        {
            int n = tid >> 3, seg = (tid & 7) * 4;
            size_t gi = ((size_t)b * SEQ + q0 + n) * SEQ + m0 + seg;
            float4 bv = *(const float4*)&bias[gi];
            float mf[4];
            if (mint) {
                int4 mi = *(const int4*)&((const int*)mask)[gi];
                mf[0]=mi.x?1.f:0.f; mf[1]=mi.y?1.f:0.f;
                mf[2]=mi.z?1.f:0.f; mf[3]=mi.w?1.f:0.f;
            } else {
                uchar4 mu = *(const uchar4*)&mask[gi];
                mf[0]=mu.x?1.f:0.f; mf[1]=mu.y?1.f:0.f;
                mf[2]=mu.z?1.f:0.f; mf[3]=mu.w?1.f:0.f;
            }
#pragma unroll
            for (int j = 0; j < 4; j++) MKb[n * 32 + seg + j] = (unsigned char)mf[j];
            __half* TH = (__half*)(sm + O_ST);
            st_h2(TH + n * SSTR + seg,     mf[0] * bv.x, mf[1] * bv.y);
            st_h2(TH + n * SSTR + seg + 2, mf[2] * bv.z, mf[3] * bv.w);
        }

        if (it + 1 < NIT) { CP_WAIT1(); } else { CP_WAIT0(); }
        __syncthreads();   /* KV(it) + MK/ST visible */

        const uint32_t kb = sb + O_KV + (it & 1) * KV_STAGE;

        /* phase A: each warp one 16x8 tile; plain (v=0), rope (v=1) */
#pragma unroll
        for (int v = 0; v < 2; v++) {
            const uint32_t uQh = sb + (v ? O_QRH : O_QH);
            const uint32_t uKh = kb + (v ? KTILE : 0);
            float acc[4];
#pragma unroll
            for (int r = 0; r < 4; r++) acc[r] = 0.f;

#pragma unroll
            for (int k16 = 0; k16 < 8; k16++) {
                int k0 = k16 * 16;
                uint32_t fAh[4], fBh[2];
                ldm_x4(fAh, uQh + (uint32_t)((wq*16 + a_r) * KSTR + k0 + a_c) * 2);
                ldm_x2(fBh, uKh + (uint32_t)((wx*8 + b_r) * KSTR + k0 + b_c) * 2);
                mma_f16(acc, fAh, fBh[0], fBh[1]);
            }
            __half* SH = (__half*)(sm + (v ? O_SR : O_SP));
#pragma unroll
            for (int half = 0; half < 2; half++) {
                int r = wq*16 + er + half*8;
                int c = wx*8 + ec;
                float f0 = (float)MKb[r*32 + c];
                float f1 = (float)MKb[r*32 + c + 1];
                st_h2(SH + r*SSTR + c,
                      f0 * fmaxf(acc[half*2 + 0], 0.f) * inv_s,
                      f1 * fmaxf(acc[half*2 + 1], 0.f) * inv_s);
            }
        }
        __syncthreads();

        /* phase B: warp (wq, wx): rows wq*16, cols wx*32, all 3 secs */
        const uint32_t uSH[3] = {sb + O_SR, sb + O_ST, sb + O_SP};
        const uint32_t uVh = kb + 2*KTILE;
#pragma unroll
        for (int k16 = 0; k16 < 2; k16++) {
            int k0 = k16 * 16;
            uint32_t fVh[2][4];
#pragma unroll
            for (int dh = 0; dh < 2; dh++)
                ldm_x4_t(fVh[dh], uVh + (uint32_t)((k0 + a_r) * KSTR + wx*32 + dh*16 + a_c) * 2);
#pragma unroll
            for (int sec = 0; sec < 3; sec++) {
                uint32_t fSh[4];
                ldm_x4(fSh, uSH[sec] + (uint32_t)((wq*16 + a_r) * SSTR + k0 + a_c) * 2);
#pragma unroll
                for (int j = 0; j < 4; j++)
                    mma_f16(accB[sec][j], fSh,
                            fVh[j>>1][(j&1)*2], fVh[j>>1][(j&1)*2+1]);
            }
        }
        __syncthreads();   /* all tiles consumed before next prefetch */
    }

    /* final epilogue: * gate, fp16 into ch */
#pragma unroll
    for (int sec = 0; sec < 3; sec++) {
#pragma unroll
        for (int j = 0; j < 4; j++) {
#pragma unroll
            for (int half = 0; half < 2; half++) {
                int rl = wq*16 + er + half*8;
                size_t grow = (size_t)(b * SEQ + q0 + rl);
                int d = wx*32 + j*8 + ec;
                int cx = h*384 + sec*128 + d;
                float2 g = *(const float2*)&g_fused[grow * N6 + cx];
                st_h2(ch + grow * N3 + cx,
                      accB[sec][j][half*2 + 0] * g.x,
                      accB[sec][j][half*2 + 1] * g.y);
            }
        }
    }
}

/* ---------------- RMSNorm --------------------------------------------- */
__global__ __launch_bounds__(256)
void rms_kernel(const float* __restrict__ y, const float* __restrict__ w,
                float* __restrict__ out)
{
    __shared__ float sh[8];
    __shared__ float tot;
    int row = blockIdx.x;
    const float* yr = y + (size_t)row * HID;
    float ss = 0.f;
    for (int i = threadIdx.x; i < HID; i += 256) {
        float v = yr[i];
        ss = fmaf(v, v, ss);
    }
#pragma unroll
    for (int o = 16; o > 0; o >>= 1) ss += __shfl_down_sync(0xffffffffu, ss, o);
    if ((threadIdx.x & 31) == 0) sh[threadIdx.x >> 5] = ss;
    __syncthreads();
    if (threadIdx.x == 0) {
        float t = 0.f;
#pragma unroll
        for (int i = 0; i < 8; i++) t += sh[i];
        tot = rsqrtf(t / (float)HID + 1e-6f);
    }
    __syncthreads();
    float r = tot;
    for (int i = threadIdx.x; i < HID; i += 256)
        out[(size_t)row * HID + i] = yr[i] * r * w[i];
}

/* ---------------- launch ----------------------------------------------- */
extern "C" void kernel_launch(void* const* d_in, const int* in_sizes, int n_in,
                              void* d_out, int out_size)
{
    const float*         hidden = (const float*)d_in[0];
    const unsigned char* mask   = (const unsigned char*)d_in[1];
    const float*         bias   = (const float*)d_in[2];
    const float*         Wqkvu  = (const float*)d_in[3];
    const float*         Wout   = (const float*)d_in[4];
    const float*         bout   = (const float*)d_in[5];
    const float*         rmsw   = (const float*)d_in[6];
    float*               out    = (float*)d_out;

    float *fused, *yp;
    __half *ah, *wqh, *woh, *ch;
    cudaGetSymbolAddress((void**)&fused, g_fused);
    cudaGetSymbolAddress((void**)&yp,    g_y);
    cudaGetSymbolAddress((void**)&ah,  g_ah);
    cudaGetSymbolAddress((void**)&wqh, g_wqh);
    cudaGetSymbolAddress((void**)&woh, g_woh);
    cudaGetSymbolAddress((void**)&ch,  g_ch);

    cudaFuncSetAttribute(attn_mma, cudaFuncAttributeMaxDynamicSharedMemorySize,
                         ASMEM);
    cudaFuncSetAttribute(mma_gemm<1024, 6144, 0>,
                         cudaFuncAttributeMaxDynamicSharedMemorySize, GSMEM);
    cudaFuncSetAttribute(mma_gemm<3072, 1024, 1>,
                         cudaFuncAttributeMaxDynamicSharedMemorySize, GSMEM);

    mask_detect_kernel<<<1, 256>>>(mask);

    /* conversions: everything single fp16 */
    conv_h<<<(ROWS*HID/4 + 255)/256, 256>>>(hidden, ah, ROWS*HID/4);
    conv_T<<<dim3(N6/32, HID/32), 256>>>(Wqkvu, wqh, HID, N6);
    conv_T<<<dim3(HID/32, N3/32), 256>>>(Wout, woh, N3, HID);

    /* fused QKVU GEMM: silu + gate write + v/q/k routing + RoPE in epi */
    mma_gemm<1024, 6144, 0><<<dim3(48, 32), 256, GSMEM>>>(ah, wqh,
                                                          fused, nullptr, nullptr);

    /* tensor-core 3-way attention -> g_ch (gated fp16) */
    attn_mma<<<dim3(SEQ/64, NHEAD, BATCH), 512, ASMEM>>>(mask, bias, ch);

    /* y = comb @ W_out + b_out + hidden */
    mma_gemm<3072, 1024, 1><<<dim3(8, 32), 256, GSMEM>>>(ch, woh,
                                                         yp, bout, hidden);

    rms_kernel<<<ROWS, 256>>>(yp, rmsw, out);
}

// round 15
// speedup vs baseline: 2.3176x; 1.1325x over previous
#include <cuda_runtime.h>
#include <cuda_fp16.h>
#include <cstdint>
#include <math.h>

#define SEQ   2048
#define BATCH 2
#define HID   1024
#define NHEAD 8
#define HDIM  128
#define ROWS  (BATCH*SEQ)   /* 4096 */
#define N6    (6*HID)       /* 6144 */
#define N3    (3*HID)       /* 3072 */

/* ---------------- scratch (device globals; no allocation allowed) ------- */
__device__ float  g_y[(size_t)ROWS*HID];
__device__ int    g_mask_int;
__device__ float2 g_rope[(size_t)SEQ*64];          /* cos/sin table */

/* single-fp16 operands everywhere */
__device__ __half g_ah[(size_t)ROWS*HID];          /* hidden fp16 */
__device__ __half g_wqh[(size_t)N6*HID];           /* W_qkvu^T */
__device__ __half g_woh[(size_t)HID*N3];           /* W_out^T  */
__device__ __half g_ch[(size_t)ROWS*N3];           /* gated attn out */
__device__ __half g_gh[(size_t)ROWS*N3];           /* gate (silu u) fp16 */

/* attention operands, layout [row][h*128+d] */
__device__ __half g_qh[(size_t)ROWS*HID];
__device__ __half g_qrh[(size_t)ROWS*HID];
__device__ __half g_kh[(size_t)ROWS*HID];
__device__ __half g_krh[(size_t)ROWS*HID];
__device__ __half g_vh[(size_t)ROWS*HID];

/* ================= helpers ============================================= */
__device__ __forceinline__ uint32_t smem_u32(const void* p) {
    uint32_t a;
    asm("{ .reg .u64 t; cvta.to.shared.u64 t, %1; cvt.u32.u64 %0, t; }"
        : "=r"(a) : "l"(p));
    return a;
}
__device__ __forceinline__ void cp16(uint32_t saddr, const void* g) {
    asm volatile("cp.async.cg.shared.global [%0], [%1], 16;"
                 :: "r"(saddr), "l"(g));
}
#define CP_COMMIT() asm volatile("cp.async.commit_group;" ::: "memory")
#define CP_WAIT0()  asm volatile("cp.async.wait_group 0;" ::: "memory")
#define CP_WAIT1()  asm volatile("cp.async.wait_group 1;" ::: "memory")

__device__ __forceinline__ void ldm_x4(uint32_t* r, uint32_t addr) {
    asm volatile("ldmatrix.sync.aligned.m8n8.x4.shared.b16 {%0,%1,%2,%3}, [%4];"
                 : "=r"(r[0]), "=r"(r[1]), "=r"(r[2]), "=r"(r[3]) : "r"(addr));
}
__device__ __forceinline__ void ldm_x4_t(uint32_t* r, uint32_t addr) {
    asm volatile("ldmatrix.sync.aligned.m8n8.x4.trans.shared.b16 {%0,%1,%2,%3}, [%4];"
                 : "=r"(r[0]), "=r"(r[1]), "=r"(r[2]), "=r"(r[3]) : "r"(addr));
}
__device__ __forceinline__ void mma_f16(float* d,
                                        const uint32_t* a,
                                        uint32_t b0, uint32_t b1) {
    asm volatile("mma.sync.aligned.m16n8k16.row.col.f32.f16.f16.f32 "
                 "{%0,%1,%2,%3},{%4,%5,%6,%7},{%8,%9},{%0,%1,%2,%3};"
                 : "+f"(d[0]), "+f"(d[1]), "+f"(d[2]), "+f"(d[3])
                 : "r"(a[0]), "r"(a[1]), "r"(a[2]), "r"(a[3]), "r"(b0), "r"(b1));
}
__device__ __forceinline__ void st_h2(__half* p, float x0, float x1) {
    *(__half2*)p = __halves2half2(__float2half_rn(x0), __float2half_rn(x1));
}

/* ---------------- RoPE cos/sin table ----------------------------------- */
__global__ __launch_bounds__(256)
void rope_table_kernel()
{
    int idx = blockIdx.x * 256 + threadIdx.x;    /* SEQ*64 = 131072 */
    if (idx >= SEQ * 64) return;
    int pos = idx >> 6, i = idx & 63;
    float ang = (float)pos / powf(10000.f, (float)i / 64.f);
    float s, c;
    sincosf(ang, &s, &c);
    g_rope[idx] = make_float2(c, s);
}

/* ========== cp.async double-buffered fp16 GEMM: C = A @ B^T ============ */
/* Block 128x128, BK=32, 8 warps (2m x 4n).                                */
/* EPI 0: QKVU epilogue (silu + fp16 gate/v/q/k routing + table RoPE).     */
/* EPI 1: + bias + resid -> fp32 C.                                        */
#define TSTR   40
#define GTILE  10240                    /* 128*TSTR*2 bytes */
#define GSTAGE (2*GTILE)                /* A B */
#define GSMEM  (2*GSTAGE)               /* 40960 */

template<int KDIM, int NDIM, int EPI>
__global__ __launch_bounds__(256)
void mma_gemm(const __half* __restrict__ Ah, const __half* __restrict__ Bh,
              float* __restrict__ C,
              const float* __restrict__ bias, const float* __restrict__ resid)
{
    extern __shared__ char dsm[];
    const uint32_t sb = smem_u32(dsm);

    const int tid  = threadIdx.x;
    const int lane = tid & 31, wid = tid >> 5;
    const int wm = wid >> 2, wn = wid & 3;
    const int m0 = blockIdx.y * 128, n0 = blockIdx.x * 128;

    const int a_r = lane & 15;
    const int a_c = (lane >> 4) * 8;
    const int b_r = (lane & 7) + ((lane >> 4) & 1) * 8;
    const int b_c = ((lane >> 3) & 1) * 8;

    float acc[4][4][4];
#pragma unroll
    for (int i = 0; i < 4; i++)
#pragma unroll
        for (int j = 0; j < 4; j++)
#pragma unroll
            for (int r = 0; r < 4; r++) acc[i][j][r] = 0.f;

    const int NC = KDIM / 32;

    /* prefetch chunk 0 */
    {
        uint32_t bs = sb;
#pragma unroll
        for (int i = 0; i < 2; i++) {
            int idx = tid + 256 * i;
            int row = idx >> 2, seg = (idx & 3) << 3;
            size_t ga = (size_t)(m0 + row) * KDIM + seg;
            size_t gb = (size_t)(n0 + row) * KDIM + seg;
            uint32_t so = (uint32_t)(row * TSTR + seg) * 2;
            cp16(bs + 0*GTILE + so, Ah + ga);
            cp16(bs + 1*GTILE + so, Bh + gb);
        }
        CP_COMMIT();
    }

    for (int ic = 0; ic < NC; ic++) {
        if (ic + 1 < NC) {
            int kc = (ic + 1) * 32;
            uint32_t bs = sb + ((ic + 1) & 1) * GSTAGE;
#pragma unroll
            for (int i = 0; i < 2; i++) {
                int idx = tid + 256 * i;
                int row = idx >> 2, seg = (idx & 3) << 3;
                size_t ga = (size_t)(m0 + row) * KDIM + kc + seg;
                size_t gb = (size_t)(n0 + row) * KDIM + kc + seg;
                uint32_t so = (uint32_t)(row * TSTR + seg) * 2;
                cp16(bs + 0*GTILE + so, Ah + ga);
                cp16(bs + 1*GTILE + so, Bh + gb);
            }
            CP_COMMIT();
            CP_WAIT1();
        } else {
            CP_WAIT0();
        }
        __syncthreads();

        const uint32_t bs = sb + (ic & 1) * GSTAGE;
        const uint32_t uAh = bs, uBh = bs + GTILE;

#pragma unroll
        for (int k0 = 0; k0 < 32; k0 += 16) {
            uint32_t fAh[4][4], fB[2][4];
#pragma unroll
            for (int mt = 0; mt < 4; mt++)
                ldm_x4(fAh[mt], uAh + (uint32_t)((wm*64 + mt*16 + a_r) * TSTR + k0 + a_c) * 2);
#pragma unroll
            for (int bp = 0; bp < 2; bp++)
                ldm_x4(fB[bp], uBh + (uint32_t)((wn*32 + bp*16 + b_r) * TSTR + k0 + b_c) * 2);
#pragma unroll
            for (int mt = 0; mt < 4; mt++)
#pragma unroll
                for (int nt = 0; nt < 4; nt++)
                    mma_f16(acc[mt][nt], fAh[mt],
                            fB[nt>>1][(nt&1)*2], fB[nt>>1][(nt&1)*2+1]);
        }
        __syncthreads();
    }

    const int er = lane >> 2, ec = (lane & 3) * 2;
#pragma unroll
    for (int mt = 0; mt < 4; mt++) {
#pragma unroll
        for (int nt = 0; nt < 4; nt++) {
            int col = n0 + wn*32 + nt*8 + ec;
#pragma unroll
            for (int half = 0; half < 2; half++) {
                size_t row = (size_t)(m0 + wm*64 + mt*16 + er + half*8);
                float v0 = acc[mt][nt][half*2 + 0];
                float v1 = acc[mt][nt][half*2 + 1];
                if (EPI == 0) {
                    float s0 = v0 / (1.f + expf(-v0));
                    float s1 = v1 / (1.f + expf(-v1));
                    if (col < 3*HID) {
                        st_h2(&g_gh[row*N3 + col], s0, s1);
                    } else if (col < 4*HID) {
                        int d = col - 3*HID;
                        st_h2(&g_vh[row*HID + d], s0, s1);
                    } else {
                        /* q or k: fused RoPE via table on (2i, 2i+1) pair */
                        int d = col & (HID - 1);
                        int i = (d & 127) >> 1;
                        float2 cs = g_rope[(row & (SEQ - 1)) * 64 + i];
                        float r0 = s0 * cs.x - s1 * cs.y;
                        float r1 = s1 * cs.x + s0 * cs.y;
                        size_t o = row * HID + d;
                        if (col < 5*HID) {
                            st_h2(&g_qh[o],  s0, s1);
                            st_h2(&g_qrh[o], r0, r1);
                        } else {
                            st_h2(&g_kh[o],  s0, s1);
                            st_h2(&g_krh[o], r0, r1);
                        }
                    }
                } else {
                    size_t rb = row * NDIM + col;
                    float2 o;
                    o.x = v0 + bias[col+0] + resid[rb+0];
                    o.y = v1 + bias[col+1] + resid[rb+1];
                    *(float2*)&C[row * NDIM + col] = o;
                }
            }
        }
    }
}

/* ============ conversions ============================================== */
__global__ __launch_bounds__(256)
void conv_h(const float* __restrict__ A, __half* __restrict__ H, int n4)
{
    int i = blockIdx.x * 256 + threadIdx.x;
    if (i >= n4) return;
    float4 v = *(const float4*)(A + (size_t)i * 4);
    st_h2(H + (size_t)i*4,     v.x, v.y);
    st_h2(H + (size_t)i*4 + 2, v.z, v.w);
}

/* W [K][N] row-major -> T [N][K] fp16 */
__global__ __launch_bounds__(256)
void conv_T(const float* __restrict__ W, __half* __restrict__ Th, int K, int N)
{
    __shared__ float t[32][33];
    int kb = blockIdx.y * 32, nb = blockIdx.x * 32;
    int tx = threadIdx.x & 31, ty = threadIdx.x >> 5;
#pragma unroll
    for (int i = 0; i < 4; i++) {
        int k = ty + 8 * i;
        t[k][tx] = W[(size_t)(kb + k) * N + nb + tx];
    }
    __syncthreads();
#pragma unroll
    for (int i = 0; i < 4; i++) {
        int n = ty + 8 * i;
        Th[(size_t)(nb + n) * K + kb + tx] = __float2half_rn(t[tx][n]);
    }
}

/* ---------------- mask dtype detector ---------------------------------- */
__global__ void mask_detect_kernel(const unsigned char* __restrict__ mask)
{
    __shared__ int cnt;
    if (threadIdx.x == 0) cnt = 0;
    __syncthreads();
    int c = 0;
    for (int i = threadIdx.x; i < 16384; i += 256) c += (mask[i] != 0);
    atomicAdd(&cnt, c);
    __syncthreads();
    if (threadIdx.x == 0) g_mask_int = (cnt < 4096) ? 1 : 0;
}

/* ---------------- tensor-core 3-way attention (m-tile 64) -------------- */
#define KSTR 136   /* Q/K/V smem row stride (halves): 128 + 8 */
#define SSTR 72    /* S smem row stride: 64 + 8 */
#define KTILE 17408 /* 64*KSTR*2 */

/* smem byte offsets */
#define O_QH   0
#define O_QRH  17408
#define O_KV   34816
#define KV_STAGE (3*KTILE)      /* kh, krh, vh = 52224; 2 stages end 139264 */
#define O_SR   139264           /* 64*SSTR*2 = 9216 each */
#define O_ST   148480
#define O_SP   157696
#define O_MK   166912           /* 64*64 = 4096 */
#define ASMEM  171008

__global__ __launch_bounds__(512)
void attn_mma(const unsigned char* __restrict__ mask,
              const float* __restrict__ bias,
              __half* __restrict__ ch)
{
    extern __shared__ char sm[];
    const uint32_t sb = smem_u32(sm);
    unsigned char* MKb = (unsigned char*)(sm + O_MK);

    const int b = blockIdx.z, h = blockIdx.y, q0 = blockIdx.x * 64;
    const int tid = threadIdx.x, lane = tid & 31, wid = tid >> 5;
    const int wq = wid >> 2, wx = wid & 3;     /* 16 warps: 4 q-sub x 4 x */
    const int mint = g_mask_int;
    const float inv_s = 1.0f / (float)SEQ;

    const int a_r = lane & 15, a_c = (lane >> 4) * 8;
    const int b_r = (lane & 7) + ((lane >> 4) & 1) * 8;
    const int b_c = ((lane >> 3) & 1) * 8;
    const int er  = lane >> 2, ec  = (lane & 3) * 2;

    /* persistent Q tiles (q, qr): 64 rows x 128 cols, 1024 chunks each */
#pragma unroll
    for (int i = 0; i < 2; i++) {
        int c = tid + 512 * i;
        int row = c >> 4, seg = (c & 15) * 8;
        size_t g = (size_t)(b * SEQ + q0 + row) * HID + h * 128 + seg;
        int so = (row * KSTR + seg) * 2;
        *(uint4*)(sm + O_QH  + so) = *(const uint4*)&g_qh[g];
        *(uint4*)(sm + O_QRH + so) = *(const uint4*)&g_qrh[g];
    }

    float accB[3][4][4];
#pragma unroll
    for (int s = 0; s < 3; s++)
#pragma unroll
        for (int j = 0; j < 4; j++)
#pragma unroll
            for (int r = 0; r < 4; r++) accB[s][j][r] = 0.f;

    const int NIT = SEQ / 64;

    /* prefetch KV tiles for m-iter 0: 3 tiles x 1024 chunks */
    {
        uint32_t bs = sb + O_KV;
#pragma unroll
        for (int i = 0; i < 2; i++) {
            int c = tid + 512 * i;
            int row = c >> 4, seg = (c & 15) * 8;
            size_t g = (size_t)(b * SEQ + row) * HID + h * 128 + seg;
            uint32_t so = (uint32_t)(row * KSTR + seg) * 2;
            cp16(bs + 0*KTILE + so, g_kh  + g);
            cp16(bs + 1*KTILE + so, g_krh + g);
            cp16(bs + 2*KTILE + so, g_vh  + g);
        }
        CP_COMMIT();
    }
    __syncthreads();   /* Q tiles visible */

    for (int it = 0; it < NIT; it++) {
        const int m0 = it * 64;

        /* prefetch next m-tile */
        if (it + 1 < NIT) {
            uint32_t bs = sb + O_KV + ((it + 1) & 1) * KV_STAGE;
            int mn = (it + 1) * 64;
#pragma unroll
            for (int i = 0; i < 2; i++) {
                int c = tid + 512 * i;
                int row = c >> 4, seg = (c & 15) * 8;
                size_t g = (size_t)(b * SEQ + mn + row) * HID + h * 128 + seg;
                uint32_t so = (uint32_t)(row * KSTR + seg) * 2;
                cp16(bs + 0*KTILE + so, g_kh  + g);
                cp16(bs + 1*KTILE + so, g_krh + g);
                cp16(bs + 2*KTILE + so, g_vh  + g);
            }
            CP_COMMIT();
        }

        /* mask tile + ts scores: 64x64 entries, 8 per thread */
        {
            int n = tid >> 3, seg = (tid & 7) * 8;
            size_t gi = ((size_t)b * SEQ + q0 + n) * SEQ + m0 + seg;
            float4 b0 = *(const float4*)&bias[gi];
            float4 b1 = *(const float4*)&bias[gi + 4];
            float mf[8];
            if (mint) {
                int4 m0i = *(const int4*)&((const int*)mask)[gi];
                int4 m1i = *(const int4*)&((const int*)mask)[gi + 4];
                mf[0]=m0i.x?1.f:0.f; mf[1]=m0i.y?1.f:0.f; mf[2]=m0i.z?1.f:0.f; mf[3]=m0i.w?1.f:0.f;
                mf[4]=m1i.x?1.f:0.f; mf[5]=m1i.y?1.f:0.f; mf[6]=m1i.z?1.f:0.f; mf[7]=m1i.w?1.f:0.f;
            } else {
                uchar4 m0u = *(const uchar4*)&mask[gi];
                uchar4 m1u = *(const uchar4*)&mask[gi + 4];
                mf[0]=m0u.x?1.f:0.f; mf[1]=m0u.y?1.f:0.f; mf[2]=m0u.z?1.f:0.f; mf[3]=m0u.w?1.f:0.f;
                mf[4]=m1u.x?1.f:0.f; mf[5]=m1u.y?1.f:0.f; mf[6]=m1u.z?1.f:0.f; mf[7]=m1u.w?1.f:0.f;
            }
#pragma unroll
            for (int j = 0; j < 8; j++) MKb[n * 64 + seg + j] = (unsigned char)mf[j];
            float bv[8] = {b0.x, b0.y, b0.z, b0.w, b1.x, b1.y, b1.z, b1.w};
            __half* TH = (__half*)(sm + O_ST);
#pragma unroll
            for (int j = 0; j < 8; j += 2)
                st_h2(TH + n * SSTR + seg + j, mf[j] * bv[j], mf[j+1] * bv[j+1]);
        }

        if (it + 1 < NIT) { CP_WAIT1(); } else { CP_WAIT0(); }
        __syncthreads();   /* KV(it) + MK/ST visible */

        const uint32_t kb = sb + O_KV + (it & 1) * KV_STAGE;

        /* phase A: each warp 16x16 (2 mma per ldm pair); plain, rope */
#pragma unroll
        for (int v = 0; v < 2; v++) {
            const uint32_t uQh = sb + (v ? O_QRH : O_QH);
            const uint32_t uKh = kb + (v ? KTILE : 0);
            float acc[2][4];
#pragma unroll
            for (int t = 0; t < 2; t++)
#pragma unroll
                for (int r = 0; r < 4; r++) acc[t][r] = 0.f;

#pragma unroll
            for (int k16 = 0; k16 < 8; k16++) {
                int k0 = k16 * 16;
                uint32_t fA[4], fB[4];
                ldm_x4(fA, uQh + (uint32_t)((wq*16 + a_r) * KSTR + k0 + a_c) * 2);
                ldm_x4(fB, uKh + (uint32_t)((wx*16 + b_r) * KSTR + k0 + b_c) * 2);
                mma_f16(acc[0], fA, fB[0], fB[1]);
                mma_f16(acc[1], fA, fB[2], fB[3]);
            }
            __half* SH = (__half*)(sm + (v ? O_SR : O_SP));
#pragma unroll
            for (int nb = 0; nb < 2; nb++) {
#pragma unroll
                for (int half = 0; half < 2; half++) {
                    int r = wq*16 + er + half*8;
                    int c = wx*16 + nb*8 + ec;
                    float f0 = (float)MKb[r*64 + c];
                    float f1 = (float)MKb[r*64 + c + 1];
                    st_h2(SH + r*SSTR + c,
                          f0 * fmaxf(acc[nb][half*2 + 0], 0.f) * inv_s,
                          f1 * fmaxf(acc[nb][half*2 + 1], 0.f) * inv_s);
                }
            }
        }
        __syncthreads();

        /* phase B: warp (wq, wx): rows wq*16, cols wx*32, all 3 secs; K=64 */
        const uint32_t uSH[3] = {sb + O_SR, sb + O_ST, sb + O_SP};
        const uint32_t uVh = kb + 2*KTILE;
#pragma unroll
        for (int k16 = 0; k16 < 4; k16++) {
            int k0 = k16 * 16;
            uint32_t fVh[2][4];
#pragma unroll
            for (int dh = 0; dh < 2; dh++)
                ldm_x4_t(fVh[dh], uVh + (uint32_t)((k0 + a_r) * KSTR + wx*32 + dh*16 + a_c) * 2);
#pragma unroll
            for (int sec = 0; sec < 3; sec++) {
                uint32_t fSh[4];
                ldm_x4(fSh, uSH[sec] + (uint32_t)((wq*16 + a_r) * SSTR + k0 + a_c) * 2);
#pragma unroll
                for (int j = 0; j < 4; j++)
                    mma_f16(accB[sec][j], fSh,
                            fVh[j>>1][(j&1)*2], fVh[j>>1][(j&1)*2+1]);
            }
        }
        __syncthreads();   /* all tiles consumed before next prefetch */
    }

    /* final epilogue: * gate (fp16), fp16 into ch */
#pragma unroll
    for (int sec = 0; sec < 3; sec++) {
#pragma unroll
        for (int j = 0; j < 4; j++) {
#pragma unroll
            for (int half = 0; half < 2; half++) {
                int rl = wq*16 + er + half*8;
                size_t grow = (size_t)(b * SEQ + q0 + rl);
                int d = wx*32 + j*8 + ec;
                int cx = h*384 + sec*128 + d;
                __half2 gh2 = *(const __half2*)&g_gh[grow * N3 + cx];
                float2 g = __half22float2(gh2);
                st_h2(ch + grow * N3 + cx,
                      accB[sec][j][half*2 + 0] * g.x,
                      accB[sec][j][half*2 + 1] * g.y);
            }
        }
    }
}

/* ---------------- RMSNorm --------------------------------------------- */
__global__ __launch_bounds__(256)
void rms_kernel(const float* __restrict__ y, const float* __restrict__ w,
                float* __restrict__ out)
{
    __shared__ float sh[8];
    __shared__ float tot;
    int row = blockIdx.x;
    const float* yr = y + (size_t)row * HID;
    float ss = 0.f;
    for (int i = threadIdx.x; i < HID; i += 256) {
        float v = yr[i];
        ss = fmaf(v, v, ss);
    }
#pragma unroll
    for (int o = 16; o > 0; o >>= 1) ss += __shfl_down_sync(0xffffffffu, ss, o);
    if ((threadIdx.x & 31) == 0) sh[threadIdx.x >> 5] = ss;
    __syncthreads();
    if (threadIdx.x == 0) {
        float t = 0.f;
#pragma unroll
        for (int i = 0; i < 8; i++) t += sh[i];
        tot = rsqrtf(t / (float)HID + 1e-6f);
    }
    __syncthreads();
    float r = tot;
    for (int i = threadIdx.x; i < HID; i += 256)
        out[(size_t)row * HID + i] = yr[i] * r * w[i];
}

/* ---------------- launch ----------------------------------------------- */
extern "C" void kernel_launch(void* const* d_in, const int* in_sizes, int n_in,
                              void* d_out, int out_size)
{
    const float*         hidden = (const float*)d_in[0];
    const unsigned char* mask   = (const unsigned char*)d_in[1];
    const float*         bias   = (const float*)d_in[2];
    const float*         Wqkvu  = (const float*)d_in[3];
    const float*         Wout   = (const float*)d_in[4];
    const float*         bout   = (const float*)d_in[5];
    const float*         rmsw   = (const float*)d_in[6];
    float*               out    = (float*)d_out;

    float *yp;
    __half *ah, *wqh, *woh, *ch;
    cudaGetSymbolAddress((void**)&yp,  g_y);
    cudaGetSymbolAddress((void**)&ah,  g_ah);
    cudaGetSymbolAddress((void**)&wqh, g_wqh);
    cudaGetSymbolAddress((void**)&woh, g_woh);
    cudaGetSymbolAddress((void**)&ch,  g_ch);

    cudaFuncSetAttribute(attn_mma, cudaFuncAttributeMaxDynamicSharedMemorySize,
                         ASMEM);
    cudaFuncSetAttribute(mma_gemm<1024, 6144, 0>,
                         cudaFuncAttributeMaxDynamicSharedMemorySize, GSMEM);
    cudaFuncSetAttribute(mma_gemm<3072, 1024, 1>,
                         cudaFuncAttributeMaxDynamicSharedMemorySize, GSMEM);

    mask_detect_kernel<<<1, 256>>>(mask);
    rope_table_kernel<<<(SEQ*64)/256, 256>>>();

    /* conversions: everything single fp16 */
    conv_h<<<(ROWS*HID/4 + 255)/256, 256>>>(hidden, ah, ROWS*HID/4);
    conv_T<<<dim3(N6/32, HID/32), 256>>>(Wqkvu, wqh, HID, N6);
    conv_T<<<dim3(HID/32, N3/32), 256>>>(Wout, woh, N3, HID);

    /* fused QKVU GEMM: silu + fp16 gate/v/q/k routing + table RoPE in epi */
    mma_gemm<1024, 6144, 0><<<dim3(48, 32), 256, GSMEM>>>(ah, wqh,
                                                          nullptr, nullptr, nullptr);

    /* tensor-core 3-way attention -> g_ch (gated fp16) */
    attn_mma<<<dim3(SEQ/64, NHEAD, BATCH), 512, ASMEM>>>(mask, bias, ch);

    /* y = comb @ W_out + b_out + hidden */
    mma_gemm<3072, 1024, 1><<<dim3(8, 32), 256, GSMEM>>>(ch, woh,
                                                         yp, bout, hidden);

    rms_kernel<<<ROWS, 256>>>(yp, rmsw, out);
}

// round 16
// speedup vs baseline: 2.5177x; 1.0863x over previous
#include <cuda_runtime.h>
#include <cuda_fp16.h>
#include <cstdint>
#include <math.h>

#define SEQ   2048
#define BATCH 2
#define HID   1024
#define NHEAD 8
#define HDIM  128
#define ROWS  (BATCH*SEQ)   /* 4096 */
#define N6    (6*HID)       /* 6144 */
#define N3    (3*HID)       /* 3072 */

/* ---------------- scratch (device globals; no allocation allowed) ------- */
__device__ float  g_y[(size_t)ROWS*HID];
__device__ int    g_mask_int;
__device__ float2 g_rope[(size_t)SEQ*64];          /* cos/sin table */

/* single-fp16 operands everywhere */
__device__ __half g_ah[(size_t)ROWS*HID];          /* hidden fp16 */
__device__ __half g_wqh[(size_t)N6*HID];           /* W_qkvu^T */
__device__ __half g_woh[(size_t)HID*N3];           /* W_out^T  */
__device__ __half g_ch[(size_t)ROWS*N3];           /* gated attn out */
__device__ __half g_gh[(size_t)ROWS*N3];           /* gate (silu u) fp16 */

/* attention operands, layout [row][h*128+d] */
__device__ __half g_qh[(size_t)ROWS*HID];
__device__ __half g_qrh[(size_t)ROWS*HID];
__device__ __half g_kh[(size_t)ROWS*HID];
__device__ __half g_krh[(size_t)ROWS*HID];
__device__ __half g_vh[(size_t)ROWS*HID];

/* ================= helpers ============================================= */
__device__ __forceinline__ uint32_t smem_u32(const void* p) {
    uint32_t a;
    asm("{ .reg .u64 t; cvta.to.shared.u64 t, %1; cvt.u32.u64 %0, t; }"
        : "=r"(a) : "l"(p));
    return a;
}
__device__ __forceinline__ void cp16(uint32_t saddr, const void* g) {
    asm volatile("cp.async.cg.shared.global [%0], [%1], 16;"
                 :: "r"(saddr), "l"(g));
}
#define CP_COMMIT() asm volatile("cp.async.commit_group;" ::: "memory")
#define CP_WAIT0()  asm volatile("cp.async.wait_group 0;" ::: "memory")
#define CP_WAIT1()  asm volatile("cp.async.wait_group 1;" ::: "memory")

__device__ __forceinline__ void ldm_x4(uint32_t* r, uint32_t addr) {
    asm volatile("ldmatrix.sync.aligned.m8n8.x4.shared.b16 {%0,%1,%2,%3}, [%4];"
                 : "=r"(r[0]), "=r"(r[1]), "=r"(r[2]), "=r"(r[3]) : "r"(addr));
}
__device__ __forceinline__ void ldm_x4_t(uint32_t* r, uint32_t addr) {
    asm volatile("ldmatrix.sync.aligned.m8n8.x4.trans.shared.b16 {%0,%1,%2,%3}, [%4];"
                 : "=r"(r[0]), "=r"(r[1]), "=r"(r[2]), "=r"(r[3]) : "r"(addr));
}
__device__ __forceinline__ void mma_f16(float* d,
                                        const uint32_t* a,
                                        uint32_t b0, uint32_t b1) {
    asm volatile("mma.sync.aligned.m16n8k16.row.col.f32.f16.f16.f32 "
                 "{%0,%1,%2,%3},{%4,%5,%6,%7},{%8,%9},{%0,%1,%2,%3};"
                 : "+f"(d[0]), "+f"(d[1]), "+f"(d[2]), "+f"(d[3])
                 : "r"(a[0]), "r"(a[1]), "r"(a[2]), "r"(a[3]), "r"(b0), "r"(b1));
}
__device__ __forceinline__ void st_h2(__half* p, float x0, float x1) {
    *(__half2*)p = __halves2half2(__float2half_rn(x0), __float2half_rn(x1));
}

/* ========== merged prologue: mask detect, rope table, conversions ====== */
#define PB_MASK  0
#define PB_ROPE  1                       /* 512 blocks  */
#define PB_CONVH (PB_ROPE + 512)         /* 4096 blocks */
#define PB_WQ    (PB_CONVH + 4096)       /* 6144 blocks */
#define PB_WO    (PB_WQ + 6144)          /* 3072 blocks */
#define PB_TOT   (PB_WO + 3072)

__device__ __forceinline__ void conv_T_block(const float* __restrict__ W,
                                             __half* __restrict__ Th,
                                             int K, int N, int bx, int by)
{
    __shared__ float t[32][33];
    int kb = by * 32, nb = bx * 32;
    int tx = threadIdx.x & 31, ty = threadIdx.x >> 5;
#pragma unroll
    for (int i = 0; i < 4; i++) {
        int k = ty + 8 * i;
        t[k][tx] = W[(size_t)(kb + k) * N + nb + tx];
    }
    __syncthreads();
#pragma unroll
    for (int i = 0; i < 4; i++) {
        int n = ty + 8 * i;
        Th[(size_t)(nb + n) * K + kb + tx] = __float2half_rn(t[tx][n]);
    }
}

__global__ __launch_bounds__(256)
void prep_kernel(const float* __restrict__ hidden,
                 const unsigned char* __restrict__ mask,
                 const float* __restrict__ Wqkvu,
                 const float* __restrict__ Wout)
{
    int blk = blockIdx.x;
    if (blk == PB_MASK) {
        __shared__ int cnt;
        if (threadIdx.x == 0) cnt = 0;
        __syncthreads();
        int c = 0;
        for (int i = threadIdx.x; i < 16384; i += 256) c += (mask[i] != 0);
        atomicAdd(&cnt, c);
        __syncthreads();
        if (threadIdx.x == 0) g_mask_int = (cnt < 4096) ? 1 : 0;
    } else if (blk < PB_CONVH) {
        int idx = (blk - PB_ROPE) * 256 + threadIdx.x;   /* SEQ*64 */
        int pos = idx >> 6, i = idx & 63;
        float ang = (float)pos / powf(10000.f, (float)i / 64.f);
        float s, c;
        sincosf(ang, &s, &c);
        g_rope[idx] = make_float2(c, s);
    } else if (blk < PB_WQ) {
        int i = (blk - PB_CONVH) * 256 + threadIdx.x;    /* ROWS*HID/4 */
        float4 v = *(const float4*)(hidden + (size_t)i * 4);
        st_h2(g_ah + (size_t)i*4,     v.x, v.y);
        st_h2(g_ah + (size_t)i*4 + 2, v.z, v.w);
    } else if (blk < PB_WO) {
        int li = blk - PB_WQ;                            /* 192 x 32 */
        conv_T_block(Wqkvu, g_wqh, HID, N6, li % 192, li / 192);
    } else {
        int li = blk - PB_WO;                            /* 32 x 96 */
        conv_T_block(Wout, g_woh, N3, HID, li % 32, li / 32);
    }
}

/* ========== cp.async double-buffered fp16 GEMM, BK=64: C = A @ B^T ===== */
/* Block 128x128, BK=64, 8 warps (2m x 4n).                                */
/* EPI 0: QKVU epilogue (silu + fp16 gate/v/q/k routing + table RoPE).     */
/* EPI 1: + bias + resid -> fp32 C.                                        */
#define TSTR   72                       /* 64 + 8 halves */
#define GTILE  18432                    /* 128*TSTR*2 bytes */
#define GSTAGE (2*GTILE)                /* A B = 36864 */
#define GSMEM  (2*GSTAGE)               /* 73728 */

template<int KDIM, int NDIM, int EPI>
__global__ __launch_bounds__(256, 2)
void mma_gemm(const __half* __restrict__ Ah, const __half* __restrict__ Bh,
              float* __restrict__ C,
              const float* __restrict__ bias, const float* __restrict__ resid)
{
    extern __shared__ char dsm[];
    const uint32_t sb = smem_u32(dsm);

    const int tid  = threadIdx.x;
    const int lane = tid & 31, wid = tid >> 5;
    const int wm = wid >> 2, wn = wid & 3;
    const int m0 = blockIdx.y * 128, n0 = blockIdx.x * 128;

    const int a_r = lane & 15;
    const int a_c = (lane >> 4) * 8;
    const int b_r = (lane & 7) + ((lane >> 4) & 1) * 8;
    const int b_c = ((lane >> 3) & 1) * 8;

    float acc[4][4][4];
#pragma unroll
    for (int i = 0; i < 4; i++)
#pragma unroll
        for (int j = 0; j < 4; j++)
#pragma unroll
            for (int r = 0; r < 4; r++) acc[i][j][r] = 0.f;

    const int NC = KDIM / 64;

    /* prefetch chunk 0: 128 rows x 64 halves per tile = 1024 chunks */
    {
        uint32_t bs = sb;
#pragma unroll
        for (int i = 0; i < 4; i++) {
            int idx = tid + 256 * i;
            int row = idx >> 3, seg = (idx & 7) << 3;
            size_t ga = (size_t)(m0 + row) * KDIM + seg;
            size_t gb = (size_t)(n0 + row) * KDIM + seg;
            uint32_t so = (uint32_t)(row * TSTR + seg) * 2;
            cp16(bs + 0*GTILE + so, Ah + ga);
            cp16(bs + 1*GTILE + so, Bh + gb);
        }
        CP_COMMIT();
    }

    for (int ic = 0; ic < NC; ic++) {
        if (ic + 1 < NC) {
            int kc = (ic + 1) * 64;
            uint32_t bs = sb + ((ic + 1) & 1) * GSTAGE;
#pragma unroll
            for (int i = 0; i < 4; i++) {
                int idx = tid + 256 * i;
                int row = idx >> 3, seg = (idx & 7) << 3;
                size_t ga = (size_t)(m0 + row) * KDIM + kc + seg;
                size_t gb = (size_t)(n0 + row) * KDIM + kc + seg;
                uint32_t so = (uint32_t)(row * TSTR + seg) * 2;
                cp16(bs + 0*GTILE + so, Ah + ga);
                cp16(bs + 1*GTILE + so, Bh + gb);
            }
            CP_COMMIT();
            CP_WAIT1();
        } else {
            CP_WAIT0();
        }
        __syncthreads();

        const uint32_t bs = sb + (ic & 1) * GSTAGE;
        const uint32_t uAh = bs, uBh = bs + GTILE;

#pragma unroll
        for (int k0 = 0; k0 < 64; k0 += 16) {
            uint32_t fAh[4][4], fB[2][4];
#pragma unroll
            for (int mt = 0; mt < 4; mt++)
                ldm_x4(fAh[mt], uAh + (uint32_t)((wm*64 + mt*16 + a_r) * TSTR + k0 + a_c) * 2);
#pragma unroll
            for (int bp = 0; bp < 2; bp++)
                ldm_x4(fB[bp], uBh + (uint32_t)((wn*32 + bp*16 + b_r) * TSTR + k0 + b_c) * 2);
#pragma unroll
            for (int mt = 0; mt < 4; mt++)
#pragma unroll
                for (int nt = 0; nt < 4; nt++)
                    mma_f16(acc[mt][nt], fAh[mt],
                            fB[nt>>1][(nt&1)*2], fB[nt>>1][(nt&1)*2+1]);
        }
        __syncthreads();
    }

    const int er = lane >> 2, ec = (lane & 3) * 2;
#pragma unroll
    for (int mt = 0; mt < 4; mt++) {
#pragma unroll
        for (int nt = 0; nt < 4; nt++) {
            int col = n0 + wn*32 + nt*8 + ec;
#pragma unroll
            for (int half = 0; half < 2; half++) {
                size_t row = (size_t)(m0 + wm*64 + mt*16 + er + half*8);
                float v0 = acc[mt][nt][half*2 + 0];
                float v1 = acc[mt][nt][half*2 + 1];
                if (EPI == 0) {
                    float s0 = v0 / (1.f + expf(-v0));
                    float s1 = v1 / (1.f + expf(-v1));
                    if (col < 3*HID) {
                        st_h2(&g_gh[row*N3 + col], s0, s1);
                    } else if (col < 4*HID) {
                        int d = col - 3*HID;
                        st_h2(&g_vh[row*HID + d], s0, s1);
                    } else {
                        /* q or k: fused RoPE via table on (2i, 2i+1) pair */
                        int d = col & (HID - 1);
                        int i = (d & 127) >> 1;
                        float2 cs = g_rope[(row & (SEQ - 1)) * 64 + i];
                        float r0 = s0 * cs.x - s1 * cs.y;
                        float r1 = s1 * cs.x + s0 * cs.y;
                        size_t o = row * HID + d;
                        if (col < 5*HID) {
                            st_h2(&g_qh[o],  s0, s1);
                            st_h2(&g_qrh[o], r0, r1);
                        } else {
                            st_h2(&g_kh[o],  s0, s1);
                            st_h2(&g_krh[o], r0, r1);
                        }
                    }
                } else {
                    size_t rb = row * NDIM + col;
                    float2 o;
                    o.x = v0 + bias[col+0] + resid[rb+0];
                    o.y = v1 + bias[col+1] + resid[rb+1];
                    *(float2*)&C[row * NDIM + col] = o;
                }
            }
        }
    }
}

/* ---------------- tensor-core 3-way attention (m-tile 64) -------------- */
#define KSTR 136   /* Q/K/V smem row stride (halves): 128 + 8 */
#define SSTR 72    /* S smem row stride: 64 + 8 */
#define KTILE 17408 /* 64*KSTR*2 */

/* smem byte offsets */
#define O_QH   0
#define O_QRH  17408
#define O_KV   34816
#define KV_STAGE (3*KTILE)      /* kh, krh, vh = 52224; 2 stages end 139264 */
#define O_SR   139264           /* 64*SSTR*2 = 9216 each */
#define O_ST   148480
#define O_SP   157696
#define O_MK   166912           /* 64*64 = 4096 */
#define ASMEM  171008

__global__ __launch_bounds__(512)
void attn_mma(const unsigned char* __restrict__ mask,
              const float* __restrict__ bias,
              __half* __restrict__ ch)
{
    extern __shared__ char sm[];
    const uint32_t sb = smem_u32(sm);
    unsigned char* MKb = (unsigned char*)(sm + O_MK);

    const int b = blockIdx.z, h = blockIdx.y, q0 = blockIdx.x * 64;
    const int tid = threadIdx.x, lane = tid & 31, wid = tid >> 5;
    const int wq = wid >> 2, wx = wid & 3;     /* 16 warps: 4 q-sub x 4 x */
    const int mint = g_mask_int;
    const float inv_s = 1.0f / (float)SEQ;

    const int a_r = lane & 15, a_c = (lane >> 4) * 8;
    const int b_r = (lane & 7) + ((lane >> 4) & 1) * 8;
    const int b_c = ((lane >> 3) & 1) * 8;
    const int er  = lane >> 2, ec  = (lane & 3) * 2;

    /* persistent Q tiles (q, qr): 64 rows x 128 cols, 1024 chunks each */
#pragma unroll
    for (int i = 0; i < 2; i++) {
        int c = tid + 512 * i;
        int row = c >> 4, seg = (c & 15) * 8;
        size_t g = (size_t)(b * SEQ + q0 + row) * HID + h * 128 + seg;
        int so = (row * KSTR + seg) * 2;
        *(uint4*)(sm + O_QH  + so) = *(const uint4*)&g_qh[g];
        *(uint4*)(sm + O_QRH + so) = *(const uint4*)&g_qrh[g];
    }

    float accB[3][4][4];
#pragma unroll
    for (int s = 0; s < 3; s++)
#pragma unroll
        for (int j = 0; j < 4; j++)
#pragma unroll
            for (int r = 0; r < 4; r++) accB[s][j][r] = 0.f;

    const int NIT = SEQ / 64;

    /* prefetch KV tiles for m-iter 0: 3 tiles x 1024 chunks */
    {
        uint32_t bs = sb + O_KV;
#pragma unroll
        for (int i = 0; i < 2; i++) {
            int c = tid + 512 * i;
            int row = c >> 4, seg = (c & 15) * 8;
            size_t g = (size_t)(b * SEQ + row) * HID + h * 128 + seg;
            uint32_t so = (uint32_t)(row * KSTR + seg) * 2;
            cp16(bs + 0*KTILE + so, g_kh  + g);
            cp16(bs + 1*KTILE + so, g_krh + g);
            cp16(bs + 2*KTILE + so, g_vh  + g);
        }
        CP_COMMIT();
    }
    __syncthreads();   /* Q tiles visible */

    for (int it = 0; it < NIT; it++) {
        const int m0 = it * 64;

        /* prefetch next m-tile */
        if (it + 1 < NIT) {
            uint32_t bs = sb + O_KV + ((it + 1) & 1) * KV_STAGE;
            int mn = (it + 1) * 64;
#pragma unroll
            for (int i = 0; i < 2; i++) {
                int c = tid + 512 * i;
                int row = c >> 4, seg = (c & 15) * 8;
                size_t g = (size_t)(b * SEQ + mn + row) * HID + h * 128 + seg;
                uint32_t so = (uint32_t)(row * KSTR + seg) * 2;
                cp16(bs + 0*KTILE + so, g_kh  + g);
                cp16(bs + 1*KTILE + so, g_krh + g);
                cp16(bs + 2*KTILE + so, g_vh  + g);
            }
            CP_COMMIT();
        }

        /* mask tile + ts scores: 64x64 entries, 8 per thread */
        {
            int n = tid >> 3, seg = (tid & 7) * 8;
            size_t gi = ((size_t)b * SEQ + q0 + n) * SEQ + m0 + seg;
            float4 b0 = *(const float4*)&bias[gi];
            float4 b1 = *(const float4*)&bias[gi + 4];
            float mf[8];
            if (mint) {
                int4 m0i = *(const int4*)&((const int*)mask)[gi];
                int4 m1i = *(const int4*)&((const int*)mask)[gi + 4];
                mf[0]=m0i.x?1.f:0.f; mf[1]=m0i.y?1.f:0.f; mf[2]=m0i.z?1.f:0.f; mf[3]=m0i.w?1.f:0.f;
                mf[4]=m1i.x?1.f:0.f; mf[5]=m1i.y?1.f:0.f; mf[6]=m1i.z?1.f:0.f; mf[7]=m1i.w?1.f:0.f;
            } else {
                uchar4 m0u = *(const uchar4*)&mask[gi];
                uchar4 m1u = *(const uchar4*)&mask[gi + 4];
                mf[0]=m0u.x?1.f:0.f; mf[1]=m0u.y?1.f:0.f; mf[2]=m0u.z?1.f:0.f; mf[3]=m0u.w?1.f:0.f;
                mf[4]=m1u.x?1.f:0.f; mf[5]=m1u.y?1.f:0.f; mf[6]=m1u.z?1.f:0.f; mf[7]=m1u.w?1.f:0.f;
            }
#pragma unroll
            for (int j = 0; j < 8; j++) MKb[n * 64 + seg + j] = (unsigned char)mf[j];
            float bv[8] = {b0.x, b0.y, b0.z, b0.w, b1.x, b1.y, b1.z, b1.w};
            __half* TH = (__half*)(sm + O_ST);
#pragma unroll
            for (int j = 0; j < 8; j += 2)
                st_h2(TH + n * SSTR + seg + j, mf[j] * bv[j], mf[j+1] * bv[j+1]);
        }

        if (it + 1 < NIT) { CP_WAIT1(); } else { CP_WAIT0(); }
        __syncthreads();   /* KV(it) + MK/ST visible */

        const uint32_t kb = sb + O_KV + (it & 1) * KV_STAGE;

        /* phase A: each warp 16x16 (2 mma per ldm pair); plain, rope */
#pragma unroll
        for (int v = 0; v < 2; v++) {
            const uint32_t uQh = sb + (v ? O_QRH : O_QH);
            const uint32_t uKh = kb + (v ? KTILE : 0);
            float acc[2][4];
#pragma unroll
            for (int t = 0; t < 2; t++)
#pragma unroll
                for (int r = 0; r < 4; r++) acc[t][r] = 0.f;

#pragma unroll
            for (int k16 = 0; k16 < 8; k16++) {
                int k0 = k16 * 16;
                uint32_t fA[4], fB[4];
                ldm_x4(fA, uQh + (uint32_t)((wq*16 + a_r) * KSTR + k0 + a_c) * 2);
                ldm_x4(fB, uKh + (uint32_t)((wx*16 + b_r) * KSTR + k0 + b_c) * 2);
                mma_f16(acc[0], fA, fB[0], fB[1]);
                mma_f16(acc[1], fA, fB[2], fB[3]);
            }
            __half* SH = (__half*)(sm + (v ? O_SR : O_SP));
#pragma unroll
            for (int nb = 0; nb < 2; nb++) {
#pragma unroll
                for (int half = 0; half < 2; half++) {
                    int r = wq*16 + er + half*8;
                    int c = wx*16 + nb*8 + ec;
                    float f0 = (float)MKb[r*64 + c];
                    float f1 = (float)MKb[r*64 + c + 1];
                    st_h2(SH + r*SSTR + c,
                          f0 * fmaxf(acc[nb][half*2 + 0], 0.f) * inv_s,
                          f1 * fmaxf(acc[nb][half*2 + 1], 0.f) * inv_s);
                }
            }
        }
        __syncthreads();

        /* phase B: warp (wq, wx): rows wq*16, cols wx*32, all 3 secs; K=64 */
        const uint32_t uSH[3] = {sb + O_SR, sb + O_ST, sb + O_SP};
        const uint32_t uVh = kb + 2*KTILE;
#pragma unroll
        for (int k16 = 0; k16 < 4; k16++) {
            int k0 = k16 * 16;
            uint32_t fVh[2][4];
#pragma unroll
            for (int dh = 0; dh < 2; dh++)
                ldm_x4_t(fVh[dh], uVh + (uint32_t)((k0 + a_r) * KSTR + wx*32 + dh*16 + a_c) * 2);
#pragma unroll
            for (int sec = 0; sec < 3; sec++) {
                uint32_t fSh[4];
                ldm_x4(fSh, uSH[sec] + (uint32_t)((wq*16 + a_r) * SSTR + k0 + a_c) * 2);
#pragma unroll
                for (int j = 0; j < 4; j++)
                    mma_f16(accB[sec][j], fSh,
                            fVh[j>>1][(j&1)*2], fVh[j>>1][(j&1)*2+1]);
            }
        }
        __syncthreads();   /* all tiles consumed before next prefetch */
    }

    /* final epilogue: * gate (fp16), fp16 into ch */
#pragma unroll
    for (int sec = 0; sec < 3; sec++) {
#pragma unroll
        for (int j = 0; j < 4; j++) {
#pragma unroll
            for (int half = 0; half < 2; half++) {
                int rl = wq*16 + er + half*8;
                size_t grow = (size_t)(b * SEQ + q0 + rl);
                int d = wx*32 + j*8 + ec;
                int cx = h*384 + sec*128 + d;
                __half2 gh2 = *(const __half2*)&g_gh[grow * N3 + cx];
                float2 g = __half22float2(gh2);
                st_h2(ch + grow * N3 + cx,
                      accB[sec][j][half*2 + 0] * g.x,
                      accB[sec][j][half*2 + 1] * g.y);
            }
        }
    }
}

/* ---------------- RMSNorm --------------------------------------------- */
__global__ __launch_bounds__(256)
void rms_kernel(const float* __restrict__ y, const float* __restrict__ w,
                float* __restrict__ out)
{
    __shared__ float sh[8];
    __shared__ float tot;
    int row = blockIdx.x;
    const float* yr = y + (size_t)row * HID;
    float ss = 0.f;
    for (int i = threadIdx.x; i < HID; i += 256) {
        float v = yr[i];
        ss = fmaf(v, v, ss);
    }
#pragma unroll
    for (int o = 16; o > 0; o >>= 1) ss += __shfl_down_sync(0xffffffffu, ss, o);
    if ((threadIdx.x & 31) == 0) sh[threadIdx.x >> 5] = ss;
    __syncthreads();
    if (threadIdx.x == 0) {
        float t = 0.f;
#pragma unroll
        for (int i = 0; i < 8; i++) t += sh[i];
        tot = rsqrtf(t / (float)HID + 1e-6f);
    }
    __syncthreads();
    float r = tot;
    for (int i = threadIdx.x; i < HID; i += 256)
        out[(size_t)row * HID + i] = yr[i] * r * w[i];
}

/* ---------------- launch ----------------------------------------------- */
extern "C" void kernel_launch(void* const* d_in, const int* in_sizes, int n_in,
                              void* d_out, int out_size)
{
    const float*         hidden = (const float*)d_in[0];
    const unsigned char* mask   = (const unsigned char*)d_in[1];
    const float*         bias   = (const float*)d_in[2];
    const float*         Wqkvu  = (const float*)d_in[3];
    const float*         Wout   = (const float*)d_in[4];
    const float*         bout   = (const float*)d_in[5];
    const float*         rmsw   = (const float*)d_in[6];
    float*               out    = (float*)d_out;

    float *yp;
    __half *ah, *wqh, *woh, *ch;
    cudaGetSymbolAddress((void**)&yp,  g_y);
    cudaGetSymbolAddress((void**)&ah,  g_ah);
    cudaGetSymbolAddress((void**)&wqh, g_wqh);
    cudaGetSymbolAddress((void**)&woh, g_woh);
    cudaGetSymbolAddress((void**)&ch,  g_ch);

    cudaFuncSetAttribute(attn_mma, cudaFuncAttributeMaxDynamicSharedMemorySize,
                         ASMEM);
    cudaFuncSetAttribute(mma_gemm<1024, 6144, 0>,
                         cudaFuncAttributeMaxDynamicSharedMemorySize, GSMEM);
    cudaFuncSetAttribute(mma_gemm<3072, 1024, 1>,
                         cudaFuncAttributeMaxDynamicSharedMemorySize, GSMEM);

    /* merged prologue: mask detect + rope table + all fp16 conversions */
    prep_kernel<<<PB_TOT, 256>>>(hidden, mask, Wqkvu, Wout);

    /* fused QKVU GEMM: silu + fp16 gate/v/q/k routing + table RoPE in epi */
    mma_gemm<1024, 6144, 0><<<dim3(48, 32), 256, GSMEM>>>(ah, wqh,
                                                          nullptr, nullptr, nullptr);

    /* tensor-core 3-way attention -> g_ch (gated fp16) */
    attn_mma<<<dim3(SEQ/64, NHEAD, BATCH), 512, ASMEM>>>(mask, bias, ch);

    /* y = comb @ W_out + b_out + hidden */
    mma_gemm<3072, 1024, 1><<<dim3(8, 32), 256, GSMEM>>>(ch, woh,
                                                         yp, bout, hidden);

    rms_kernel<<<ROWS, 256>>>(yp, rmsw, out);
}

// round 17
// speedup vs baseline: 2.6379x; 1.0477x over previous
#include <cuda_runtime.h>
#include <cuda_fp16.h>
#include <cstdint>
#include <math.h>

#define SEQ   2048
#define BATCH 2
#define HID   1024
#define NHEAD 8
#define HDIM  128
#define ROWS  (BATCH*SEQ)   /* 4096 */
#define N6    (6*HID)       /* 6144 */
#define N3    (3*HID)       /* 3072 */

/* ---------------- scratch (device globals; no allocation allowed) ------- */
__device__ float  g_y[2*(size_t)ROWS*HID];         /* split-K partials */
__device__ int    g_mask_int;
__device__ float2 g_rope[(size_t)SEQ*64];          /* cos/sin table */

/* single-fp16 operands everywhere */
__device__ __half g_ah[(size_t)ROWS*HID];          /* hidden fp16 */
__device__ __half g_wqh[(size_t)N6*HID];           /* W_qkvu^T */
__device__ __half g_woh[(size_t)HID*N3];           /* W_out^T  */
__device__ __half g_ch[(size_t)ROWS*N3];           /* gated attn out */
__device__ __half g_gh[(size_t)ROWS*N3];           /* gate (silu u) fp16 */

/* attention operands, layout [row][h*128+d] */
__device__ __half g_qh[(size_t)ROWS*HID];
__device__ __half g_qrh[(size_t)ROWS*HID];
__device__ __half g_kh[(size_t)ROWS*HID];
__device__ __half g_krh[(size_t)ROWS*HID];
__device__ __half g_vh[(size_t)ROWS*HID];

/* ================= helpers ============================================= */
__device__ __forceinline__ uint32_t smem_u32(const void* p) {
    uint32_t a;
    asm("{ .reg .u64 t; cvta.to.shared.u64 t, %1; cvt.u32.u64 %0, t; }"
        : "=r"(a) : "l"(p));
    return a;
}
__device__ __forceinline__ void cp16(uint32_t saddr, const void* g) {
    asm volatile("cp.async.cg.shared.global [%0], [%1], 16;"
                 :: "r"(saddr), "l"(g));
}
#define CP_COMMIT() asm volatile("cp.async.commit_group;" ::: "memory")
#define CP_WAIT0()  asm volatile("cp.async.wait_group 0;" ::: "memory")
#define CP_WAIT1()  asm volatile("cp.async.wait_group 1;" ::: "memory")

__device__ __forceinline__ void ldm_x4(uint32_t* r, uint32_t addr) {
    asm volatile("ldmatrix.sync.aligned.m8n8.x4.shared.b16 {%0,%1,%2,%3}, [%4];"
                 : "=r"(r[0]), "=r"(r[1]), "=r"(r[2]), "=r"(r[3]) : "r"(addr));
}
__device__ __forceinline__ void ldm_x4_t(uint32_t* r, uint32_t addr) {
    asm volatile("ldmatrix.sync.aligned.m8n8.x4.trans.shared.b16 {%0,%1,%2,%3}, [%4];"
                 : "=r"(r[0]), "=r"(r[1]), "=r"(r[2]), "=r"(r[3]) : "r"(addr));
}
__device__ __forceinline__ void mma_f16(float* d,
                                        const uint32_t* a,
                                        uint32_t b0, uint32_t b1) {
    asm volatile("mma.sync.aligned.m16n8k16.row.col.f32.f16.f16.f32 "
                 "{%0,%1,%2,%3},{%4,%5,%6,%7},{%8,%9},{%0,%1,%2,%3};"
                 : "+f"(d[0]), "+f"(d[1]), "+f"(d[2]), "+f"(d[3])
                 : "r"(a[0]), "r"(a[1]), "r"(a[2]), "r"(a[3]), "r"(b0), "r"(b1));
}
__device__ __forceinline__ void st_h2(__half* p, float x0, float x1) {
    *(__half2*)p = __halves2half2(__float2half_rn(x0), __float2half_rn(x1));
}

/* ========== merged prologue: mask detect, rope table, conversions ====== */
#define PB_MASK  0
#define PB_ROPE  1                       /* 512 blocks  */
#define PB_CONVH (PB_ROPE + 512)         /* 4096 blocks */
#define PB_WQ    (PB_CONVH + 4096)       /* 6144 blocks */
#define PB_WO    (PB_WQ + 6144)          /* 3072 blocks */
#define PB_TOT   (PB_WO + 3072)

__device__ __forceinline__ void conv_T_block(const float* __restrict__ W,
                                             __half* __restrict__ Th,
                                             int K, int N, int bx, int by)
{
    __shared__ float t[32][33];
    int kb = by * 32, nb = bx * 32;
    int tx = threadIdx.x & 31, ty = threadIdx.x >> 5;
#pragma unroll
    for (int i = 0; i < 4; i++) {
        int k = ty + 8 * i;
        t[k][tx] = W[(size_t)(kb + k) * N + nb + tx];
    }
    __syncthreads();
#pragma unroll
    for (int i = 0; i < 4; i++) {
        int n = ty + 8 * i;
        Th[(size_t)(nb + n) * K + kb + tx] = __float2half_rn(t[tx][n]);
    }
}

__global__ __launch_bounds__(256)
void prep_kernel(const float* __restrict__ hidden,
                 const unsigned char* __restrict__ mask,
                 const float* __restrict__ Wqkvu,
                 const float* __restrict__ Wout)
{
    int blk = blockIdx.x;
    if (blk == PB_MASK) {
        __shared__ int cnt;
        if (threadIdx.x == 0) cnt = 0;
        __syncthreads();
        int c = 0;
        for (int i = threadIdx.x; i < 16384; i += 256) c += (mask[i] != 0);
        atomicAdd(&cnt, c);
        __syncthreads();
        if (threadIdx.x == 0) g_mask_int = (cnt < 4096) ? 1 : 0;
    } else if (blk < PB_CONVH) {
        int idx = (blk - PB_ROPE) * 256 + threadIdx.x;   /* SEQ*64 */
        int pos = idx >> 6, i = idx & 63;
        float ang = (float)pos / powf(10000.f, (float)i / 64.f);
        float s, c;
        sincosf(ang, &s, &c);
        g_rope[idx] = make_float2(c, s);
    } else if (blk < PB_WQ) {
        int i = (blk - PB_CONVH) * 256 + threadIdx.x;    /* ROWS*HID/4 */
        float4 v = *(const float4*)(hidden + (size_t)i * 4);
        st_h2(g_ah + (size_t)i*4,     v.x, v.y);
        st_h2(g_ah + (size_t)i*4 + 2, v.z, v.w);
    } else if (blk < PB_WO) {
        int li = blk - PB_WQ;                            /* 192 x 32 */
        conv_T_block(Wqkvu, g_wqh, HID, N6, li % 192, li / 192);
    } else {
        int li = blk - PB_WO;                            /* 32 x 96 */
        conv_T_block(Wout, g_woh, N3, HID, li % 32, li / 32);
    }
}

/* ========== cp.async double-buffered fp16 GEMM, BK=64: C = A @ B^T ===== */
/* Block 128x128, BK=64, 8 warps (2m x 4n).  LDA = row stride of A and B.  */
/* EPI 0: QKVU epilogue (silu + fp16 gate/v/q/k routing + table RoPE).     */
/* EPI 1: raw partial sum -> fp32 C (bias/resid folded into rms); the      */
/*        blockIdx.z K-offset view implements split-K.                     */
#define TSTR   72                       /* 64 + 8 halves */
#define GTILE  18432                    /* 128*TSTR*2 bytes */
#define GSTAGE (2*GTILE)                /* A B = 36864 */
#define GSMEM  (2*GSTAGE)               /* 73728 */

template<int KDIM, int LDA, int NDIM, int EPI>
__global__ __launch_bounds__(256, 2)
void mma_gemm(const __half* __restrict__ Ah, const __half* __restrict__ Bh,
              float* __restrict__ C)
{
    extern __shared__ char dsm[];
    const uint32_t sb = smem_u32(dsm);

    const int tid  = threadIdx.x;
    const int lane = tid & 31, wid = tid >> 5;
    const int wm = wid >> 2, wn = wid & 3;
    const int m0 = blockIdx.y * 128, n0 = blockIdx.x * 128;

    /* split-K view: shift A/B by z*KDIM cols, C to partial-z buffer */
    Ah += (size_t)blockIdx.z * KDIM;
    Bh += (size_t)blockIdx.z * KDIM;
    C  += (size_t)blockIdx.z * ROWS * NDIM;

    const int a_r = lane & 15;
    const int a_c = (lane >> 4) * 8;
    const int b_r = (lane & 7) + ((lane >> 4) & 1) * 8;
    const int b_c = ((lane >> 3) & 1) * 8;

    float acc[4][4][4];
#pragma unroll
    for (int i = 0; i < 4; i++)
#pragma unroll
        for (int j = 0; j < 4; j++)
#pragma unroll
            for (int r = 0; r < 4; r++) acc[i][j][r] = 0.f;

    const int NC = KDIM / 64;

    /* prefetch chunk 0: 128 rows x 64 halves per tile = 1024 chunks */
    {
        uint32_t bs = sb;
#pragma unroll
        for (int i = 0; i < 4; i++) {
            int idx = tid + 256 * i;
            int row = idx >> 3, seg = (idx & 7) << 3;
            size_t ga = (size_t)(m0 + row) * LDA + seg;
            size_t gb = (size_t)(n0 + row) * LDA + seg;
            uint32_t so = (uint32_t)(row * TSTR + seg) * 2;
            cp16(bs + 0*GTILE + so, Ah + ga);
            cp16(bs + 1*GTILE + so, Bh + gb);
        }
        CP_COMMIT();
    }

    for (int ic = 0; ic < NC; ic++) {
        if (ic + 1 < NC) {
            int kc = (ic + 1) * 64;
            uint32_t bs = sb + ((ic + 1) & 1) * GSTAGE;
#pragma unroll
            for (int i = 0; i < 4; i++) {
                int idx = tid + 256 * i;
                int row = idx >> 3, seg = (idx & 7) << 3;
                size_t ga = (size_t)(m0 + row) * LDA + kc + seg;
                size_t gb = (size_t)(n0 + row) * LDA + kc + seg;
                uint32_t so = (uint32_t)(row * TSTR + seg) * 2;
                cp16(bs + 0*GTILE + so, Ah + ga);
                cp16(bs + 1*GTILE + so, Bh + gb);
            }
            CP_COMMIT();
            CP_WAIT1();
        } else {
            CP_WAIT0();
        }
        __syncthreads();

        const uint32_t bs = sb + (ic & 1) * GSTAGE;
        const uint32_t uAh = bs, uBh = bs + GTILE;

#pragma unroll
        for (int k0 = 0; k0 < 64; k0 += 16) {
            uint32_t fAh[4][4], fB[2][4];
#pragma unroll
            for (int mt = 0; mt < 4; mt++)
                ldm_x4(fAh[mt], uAh + (uint32_t)((wm*64 + mt*16 + a_r) * TSTR + k0 + a_c) * 2);
#pragma unroll
            for (int bp = 0; bp < 2; bp++)
                ldm_x4(fB[bp], uBh + (uint32_t)((wn*32 + bp*16 + b_r) * TSTR + k0 + b_c) * 2);
#pragma unroll
            for (int mt = 0; mt < 4; mt++)
#pragma unroll
                for (int nt = 0; nt < 4; nt++)
                    mma_f16(acc[mt][nt], fAh[mt],
                            fB[nt>>1][(nt&1)*2], fB[nt>>1][(nt&1)*2+1]);
        }
        __syncthreads();
    }

    const int er = lane >> 2, ec = (lane & 3) * 2;
#pragma unroll
    for (int mt = 0; mt < 4; mt++) {
#pragma unroll
        for (int nt = 0; nt < 4; nt++) {
            int col = n0 + wn*32 + nt*8 + ec;
#pragma unroll
            for (int half = 0; half < 2; half++) {
                size_t row = (size_t)(m0 + wm*64 + mt*16 + er + half*8);
                float v0 = acc[mt][nt][half*2 + 0];
                float v1 = acc[mt][nt][half*2 + 1];
                if (EPI == 0) {
                    float s0 = v0 / (1.f + expf(-v0));
                    float s1 = v1 / (1.f + expf(-v1));
                    if (col < 3*HID) {
                        st_h2(&g_gh[row*N3 + col], s0, s1);
                    } else if (col < 4*HID) {
                        int d = col - 3*HID;
                        st_h2(&g_vh[row*HID + d], s0, s1);
                    } else {
                        /* q or k: fused RoPE via table on (2i, 2i+1) pair */
                        int d = col & (HID - 1);
                        int i = (d & 127) >> 1;
                        float2 cs = g_rope[(row & (SEQ - 1)) * 64 + i];
                        float r0 = s0 * cs.x - s1 * cs.y;
                        float r1 = s1 * cs.x + s0 * cs.y;
                        size_t o = row * HID + d;
                        if (col < 5*HID) {
                            st_h2(&g_qh[o],  s0, s1);
                            st_h2(&g_qrh[o], r0, r1);
                        } else {
                            st_h2(&g_kh[o],  s0, s1);
                            st_h2(&g_krh[o], r0, r1);
                        }
                    }
                } else {
                    float2 o; o.x = v0; o.y = v1;
                    *(float2*)&C[row * NDIM + col] = o;
                }
            }
        }
    }
}

/* ---------------- tensor-core 3-way attention (m-tile 64) -------------- */
#define KSTR 136   /* Q/K/V smem row stride (halves): 128 + 8 */
#define SSTR 72    /* S smem row stride: 64 + 8 */
#define KTILE 17408 /* 64*KSTR*2 */

/* smem byte offsets */
#define O_QH   0
#define O_QRH  17408
#define O_KV   34816
#define KV_STAGE (3*KTILE)      /* kh, krh, vh = 52224; 2 stages end 139264 */
#define O_SR   139264           /* 64*SSTR*2 = 9216 each */
#define O_ST   148480
#define O_SP   157696
#define O_MK   166912           /* 64*64 = 4096 */
#define ASMEM  171008

__global__ __launch_bounds__(512)
void attn_mma(const unsigned char* __restrict__ mask,
              const float* __restrict__ bias,
              __half* __restrict__ ch)
{
    extern __shared__ char sm[];
    const uint32_t sb = smem_u32(sm);
    unsigned char* MKb = (unsigned char*)(sm + O_MK);

    const int b = blockIdx.z, h = blockIdx.y, q0 = blockIdx.x * 64;
    const int tid = threadIdx.x, lane = tid & 31, wid = tid >> 5;
    const int wq = wid >> 2, wx = wid & 3;       /* phase B mapping */
    const int av  = wid & 1, awx = (wid >> 1) & 1; /* phase A: variant, col-half */
    const int mint = g_mask_int;
    const float inv_s = 1.0f / (float)SEQ;

    const int a_r = lane & 15, a_c = (lane >> 4) * 8;
    const int b_r = (lane & 7) + ((lane >> 4) & 1) * 8;
    const int b_c = ((lane >> 3) & 1) * 8;
    const int er  = lane >> 2, ec  = (lane & 3) * 2;

    /* persistent Q tiles (q, qr): 64 rows x 128 cols, 1024 chunks each */
#pragma unroll
    for (int i = 0; i < 2; i++) {
        int c = tid + 512 * i;
        int row = c >> 4, seg = (c & 15) * 8;
        size_t g = (size_t)(b * SEQ + q0 + row) * HID + h * 128 + seg;
        int so = (row * KSTR + seg) * 2;
        *(uint4*)(sm + O_QH  + so) = *(const uint4*)&g_qh[g];
        *(uint4*)(sm + O_QRH + so) = *(const uint4*)&g_qrh[g];
    }

    float accB[3][4][4];
#pragma unroll
    for (int s = 0; s < 3; s++)
#pragma unroll
        for (int j = 0; j < 4; j++)
#pragma unroll
            for (int r = 0; r < 4; r++) accB[s][j][r] = 0.f;

    const int NIT = SEQ / 64;

    /* prefetch KV tiles for m-iter 0: 3 tiles x 1024 chunks */
    {
        uint32_t bs = sb + O_KV;
#pragma unroll
        for (int i = 0; i < 2; i++) {
            int c = tid + 512 * i;
            int row = c >> 4, seg = (c & 15) * 8;
            size_t g = (size_t)(b * SEQ + row) * HID + h * 128 + seg;
            uint32_t so = (uint32_t)(row * KSTR + seg) * 2;
            cp16(bs + 0*KTILE + so, g_kh  + g);
            cp16(bs + 1*KTILE + so, g_krh + g);
            cp16(bs + 2*KTILE + so, g_vh  + g);
        }
        CP_COMMIT();
    }
    __syncthreads();   /* Q tiles visible */

    for (int it = 0; it < NIT; it++) {
        const int m0 = it * 64;

        /* prefetch next m-tile */
        if (it + 1 < NIT) {
            uint32_t bs = sb + O_KV + ((it + 1) & 1) * KV_STAGE;
            int mn = (it + 1) * 64;
#pragma unroll
            for (int i = 0; i < 2; i++) {
                int c = tid + 512 * i;
                int row = c >> 4, seg = (c & 15) * 8;
                size_t g = (size_t)(b * SEQ + mn + row) * HID + h * 128 + seg;
                uint32_t so = (uint32_t)(row * KSTR + seg) * 2;
                cp16(bs + 0*KTILE + so, g_kh  + g);
                cp16(bs + 1*KTILE + so, g_krh + g);
                cp16(bs + 2*KTILE + so, g_vh  + g);
            }
            CP_COMMIT();
        }

        /* mask tile + ts scores: 64x64 entries, 8 per thread */
        {
            int n = tid >> 3, seg = (tid & 7) * 8;
            size_t gi = ((size_t)b * SEQ + q0 + n) * SEQ + m0 + seg;
            float4 b0 = *(const float4*)&bias[gi];
            float4 b1 = *(const float4*)&bias[gi + 4];
            float mf[8];
            if (mint) {
                int4 m0i = *(const int4*)&((const int*)mask)[gi];
                int4 m1i = *(const int4*)&((const int*)mask)[gi + 4];
                mf[0]=m0i.x?1.f:0.f; mf[1]=m0i.y?1.f:0.f; mf[2]=m0i.z?1.f:0.f; mf[3]=m0i.w?1.f:0.f;
                mf[4]=m1i.x?1.f:0.f; mf[5]=m1i.y?1.f:0.f; mf[6]=m1i.z?1.f:0.f; mf[7]=m1i.w?1.f:0.f;
            } else {
                uchar4 m0u = *(const uchar4*)&mask[gi];
                uchar4 m1u = *(const uchar4*)&mask[gi + 4];
                mf[0]=m0u.x?1.f:0.f; mf[1]=m0u.y?1.f:0.f; mf[2]=m0u.z?1.f:0.f; mf[3]=m0u.w?1.f:0.f;
                mf[4]=m1u.x?1.f:0.f; mf[5]=m1u.y?1.f:0.f; mf[6]=m1u.z?1.f:0.f; mf[7]=m1u.w?1.f:0.f;
            }
#pragma unroll
            for (int j = 0; j < 8; j++) MKb[n * 64 + seg + j] = (unsigned char)mf[j];
            float bv[8] = {b0.x, b0.y, b0.z, b0.w, b1.x, b1.y, b1.z, b1.w};
            __half* TH = (__half*)(sm + O_ST);
#pragma unroll
            for (int j = 0; j < 8; j += 2)
                st_h2(TH + n * SSTR + seg + j, mf[j] * bv[j], mf[j+1] * bv[j+1]);
        }

        if (it + 1 < NIT) { CP_WAIT1(); } else { CP_WAIT0(); }
        __syncthreads();   /* KV(it) + MK/ST visible */

        const uint32_t kb = sb + O_KV + (it & 1) * KV_STAGE;

        /* phase A: warp-specialized by variant — each warp one 16x32 tile */
        {
            const uint32_t uQh = sb + (av ? O_QRH : O_QH);
            const uint32_t uKh = kb + (av ? KTILE : 0);
            float acc[4][4];
#pragma unroll
            for (int t = 0; t < 4; t++)
#pragma unroll
                for (int r = 0; r < 4; r++) acc[t][r] = 0.f;

#pragma unroll
            for (int k16 = 0; k16 < 8; k16++) {
                int k0 = k16 * 16;
                uint32_t fA[4], fB0[4], fB1[4];
                ldm_x4(fA,  uQh + (uint32_t)((wq*16 + a_r) * KSTR + k0 + a_c) * 2);
                ldm_x4(fB0, uKh + (uint32_t)((awx*32 + b_r) * KSTR + k0 + b_c) * 2);
                ldm_x4(fB1, uKh + (uint32_t)((awx*32 + 16 + b_r) * KSTR + k0 + b_c) * 2);
                mma_f16(acc[0], fA, fB0[0], fB0[1]);
                mma_f16(acc[1], fA, fB0[2], fB0[3]);
                mma_f16(acc[2], fA, fB1[0], fB1[1]);
                mma_f16(acc[3], fA, fB1[2], fB1[3]);
            }
            __half* SH = (__half*)(sm + (av ? O_SR : O_SP));
#pragma unroll
            for (int nb = 0; nb < 4; nb++) {
#pragma unroll
                for (int half = 0; half < 2; half++) {
                    int r = wq*16 + er + half*8;
                    int c = awx*32 + nb*8 + ec;
                    float f0 = (float)MKb[r*64 + c];
                    float f1 = (float)MKb[r*64 + c + 1];
                    st_h2(SH + r*SSTR + c,
                          f0 * fmaxf(acc[nb][half*2 + 0], 0.f) * inv_s,
                          f1 * fmaxf(acc[nb][half*2 + 1], 0.f) * inv_s);
                }
            }
        }
        __syncthreads();

        /* phase B: warp (wq, wx): rows wq*16, cols wx*32, all 3 secs; K=64 */
        const uint32_t uSH[3] = {sb + O_SR, sb + O_ST, sb + O_SP};
        const uint32_t uVh = kb + 2*KTILE;
#pragma unroll
        for (int k16 = 0; k16 < 4; k16++) {
            int k0 = k16 * 16;
            uint32_t fVh[2][4];
#pragma unroll
            for (int dh = 0; dh < 2; dh++)
                ldm_x4_t(fVh[dh], uVh + (uint32_t)((k0 + a_r) * KSTR + wx*32 + dh*16 + a_c) * 2);
#pragma unroll
            for (int sec = 0; sec < 3; sec++) {
                uint32_t fSh[4];
                ldm_x4(fSh, uSH[sec] + (uint32_t)((wq*16 + a_r) * SSTR + k0 + a_c) * 2);
#pragma unroll
                for (int j = 0; j < 4; j++)
                    mma_f16(accB[sec][j], fSh,
                            fVh[j>>1][(j&1)*2], fVh[j>>1][(j&1)*2+1]);
            }
        }
        __syncthreads();   /* all tiles consumed before next prefetch */
    }

    /* final epilogue: * gate (fp16), fp16 into ch */
#pragma unroll
    for (int sec = 0; sec < 3; sec++) {
#pragma unroll
        for (int j = 0; j < 4; j++) {
#pragma unroll
            for (int half = 0; half < 2; half++) {
                int rl = wq*16 + er + half*8;
                size_t grow = (size_t)(b * SEQ + q0 + rl);
                int d = wx*32 + j*8 + ec;
                int cx = h*384 + sec*128 + d;
                __half2 gh2 = *(const __half2*)&g_gh[grow * N3 + cx];
                float2 g = __half22float2(gh2);
                st_h2(ch + grow * N3 + cx,
                      accB[sec][j][half*2 + 0] * g.x,
                      accB[sec][j][half*2 + 1] * g.y);
            }
        }
    }
}

/* ---------------- RMSNorm (folds split-K sum + bias + residual) -------- */
__global__ __launch_bounds__(256)
void rms_kernel(const float* __restrict__ y, const float* __restrict__ bout,
                const float* __restrict__ resid, const float* __restrict__ w,
                float* __restrict__ out)
{
    __shared__ float sh[8];
    __shared__ float tot;
    int row = blockIdx.x;
    const float* y0 = y + (size_t)row * HID;
    const float* y1 = y + (size_t)ROWS * HID + (size_t)row * HID;
    const float* rr = resid + (size_t)row * HID;
    float vloc[4];
    float ss = 0.f;
#pragma unroll
    for (int j = 0; j < 4; j++) {
        int i = threadIdx.x + 256 * j;
        float v = y0[i] + y1[i] + bout[i] + rr[i];
        vloc[j] = v;
        ss = fmaf(v, v, ss);
    }
#pragma unroll
    for (int o = 16; o > 0; o >>= 1) ss += __shfl_down_sync(0xffffffffu, ss, o);
    if ((threadIdx.x & 31) == 0) sh[threadIdx.x >> 5] = ss;
    __syncthreads();
    if (threadIdx.x == 0) {
        float t = 0.f;
#pragma unroll
        for (int i = 0; i < 8; i++) t += sh[i];
        tot = rsqrtf(t / (float)HID + 1e-6f);
    }
    __syncthreads();
    float r = tot;
#pragma unroll
    for (int j = 0; j < 4; j++) {
        int i = threadIdx.x + 256 * j;
        out[(size_t)row * HID + i] = vloc[j] * r * w[i];
    }
}

/* ---------------- launch ----------------------------------------------- */
extern "C" void kernel_launch(void* const* d_in, const int* in_sizes, int n_in,
                              void* d_out, int out_size)
{
    const float*         hidden = (const float*)d_in[0];
    const unsigned char* mask   = (const unsigned char*)d_in[1];
    const float*         bias   = (const float*)d_in[2];
    const float*         Wqkvu  = (const float*)d_in[3];
    const float*         Wout   = (const float*)d_in[4];
    const float*         bout   = (const float*)d_in[5];
    const float*         rmsw   = (const float*)d_in[6];
    float*               out    = (float*)d_out;

    float *yp;
    __half *ah, *wqh, *woh, *ch;
    cudaGetSymbolAddress((void**)&yp,  g_y);
    cudaGetSymbolAddress((void**)&ah,  g_ah);
    cudaGetSymbolAddress((void**)&wqh, g_wqh);
    cudaGetSymbolAddress((void**)&woh, g_woh);
    cudaGetSymbolAddress((void**)&ch,  g_ch);

    cudaFuncSetAttribute(attn_mma, cudaFuncAttributeMaxDynamicSharedMemorySize,
                         ASMEM);
    cudaFuncSetAttribute(mma_gemm<1024, 1024, 6144, 0>,
                         cudaFuncAttributeMaxDynamicSharedMemorySize, GSMEM);
    cudaFuncSetAttribute(mma_gemm<1536, 3072, 1024, 1>,
                         cudaFuncAttributeMaxDynamicSharedMemorySize, GSMEM);

    /* merged prologue: mask detect + rope table + all fp16 conversions */
    prep_kernel<<<PB_TOT, 256>>>(hidden, mask, Wqkvu, Wout);

    /* fused QKVU GEMM: silu + fp16 gate/v/q/k routing + table RoPE in epi */
    mma_gemm<1024, 1024, 6144, 0><<<dim3(48, 32), 256, GSMEM>>>(ah, wqh, nullptr);

    /* tensor-core 3-way attention -> g_ch (gated fp16) */
    attn_mma<<<dim3(SEQ/64, NHEAD, BATCH), 512, ASMEM>>>(mask, bias, ch);

    /* y partials = comb @ W_out (split-K=2); bias+resid folded into rms */
    mma_gemm<1536, 3072, 1024, 1><<<dim3(8, 32, 2), 256, GSMEM>>>(ch, woh, yp);

    rms_kernel<<<ROWS, 256>>>(yp, bout, hidden, rmsw, out);
}